// round 1
// baseline (speedup 1.0000x reference)
#include <cuda_runtime.h>
#include <cstdint>

#define BATCH   16384
#define IN_DIM  700
#define H_ENC   2048
#define LATENT  512
#define H_DEC   2048
#define OUT_DIM 700
#define NUM_EMB 1024
#define ALPHA   0.2f

// ---------------- scratch (static __device__, no runtime allocation) --------
__device__ float g_h[BATCH * H_ENC];        // encoder hidden, reused for decoder hidden
__device__ float g_z[BATCH * LATENT];       // latent
__device__ float g_scores[BATCH * NUM_EMB]; // -2*z@emb + |e|^2
__device__ float g_q[BATCH * LATENT];       // quantized
__device__ float g_embT[NUM_EMB * LATENT];  // transposed codebook for coalesced gather
__device__ float g_embsq[NUM_EMB];          // |e_j|^2
__device__ float g_loss;                    // sum of (q-z)^2

// ---------------- tiled fp32 GEMM: C[M,N] = epi(A[M,K] @ B[K,N]) ------------
// EPI 0: C = acc + bias[n]
// EPI 1: C = leaky_relu(acc + bias[n])
// EPI 2: C = -2*acc + bias[n]          (VQ score; bias = |e_j|^2)
#define BM 128
#define BN 128
#define BK 16

template <int EPI>
__global__ __launch_bounds__(256) void gemm_kernel(
    const float* __restrict__ A, const float* __restrict__ B,
    const float* __restrict__ bias, float* __restrict__ C,
    int M, int N, int K)
{
    __shared__ float As[BK][BM + 4];
    __shared__ float Bs[BK][BN + 4];

    const int tid = threadIdx.x;          // 0..255
    const int tx  = tid & 15;             // 0..15 (N direction)
    const int ty  = tid >> 4;             // 0..15 (M direction)
    const int m0  = blockIdx.y * BM;
    const int n0  = blockIdx.x * BN;

    float acc[8][8];
#pragma unroll
    for (int i = 0; i < 8; i++)
#pragma unroll
        for (int j = 0; j < 8; j++) acc[i][j] = 0.f;

    for (int k0 = 0; k0 < K; k0 += BK) {
        // Load A tile (BMxBK): idx = i*256+tid, k = tid&15, m = i*16 + tid>>4
#pragma unroll
        for (int i = 0; i < 8; i++) {
            int k = tid & 15;
            int m = i * 16 + (tid >> 4);
            int gm = m0 + m, gk = k0 + k;
            float v = 0.f;
            if (gm < M && gk < K) v = A[(size_t)gm * K + gk];
            As[k][m] = v;
        }
        // Load B tile (BKxBN): n = tid&127, k = i*2 + tid>>7
#pragma unroll
        for (int i = 0; i < 8; i++) {
            int n = tid & 127;
            int k = i * 2 + (tid >> 7);
            int gk = k0 + k, gn = n0 + n;
            float v = 0.f;
            if (gk < K && gn < N) v = B[(size_t)gk * N + gn];
            Bs[k][n] = v;
        }
        __syncthreads();

#pragma unroll
        for (int k = 0; k < BK; k++) {
            float4 a0 = *reinterpret_cast<const float4*>(&As[k][ty * 8]);
            float4 a1 = *reinterpret_cast<const float4*>(&As[k][ty * 8 + 4]);
            float4 b0 = *reinterpret_cast<const float4*>(&Bs[k][tx * 8]);
            float4 b1 = *reinterpret_cast<const float4*>(&Bs[k][tx * 8 + 4]);
            float a[8] = {a0.x, a0.y, a0.z, a0.w, a1.x, a1.y, a1.z, a1.w};
            float b[8] = {b0.x, b0.y, b0.z, b0.w, b1.x, b1.y, b1.z, b1.w};
#pragma unroll
            for (int i = 0; i < 8; i++)
#pragma unroll
                for (int j = 0; j < 8; j++)
                    acc[i][j] += a[i] * b[j];
        }
        __syncthreads();
    }

    // Epilogue
#pragma unroll
    for (int i = 0; i < 8; i++) {
        int gm = m0 + ty * 8 + i;
        if (gm >= M) continue;
#pragma unroll
        for (int j = 0; j < 8; j++) {
            int gn = n0 + tx * 8 + j;
            if (gn >= N) continue;
            float v = acc[i][j];
            if (EPI == 2) {
                v = -2.f * v + bias[gn];
            } else {
                v += bias[gn];
                if (EPI == 1) v = (v >= 0.f) ? v : ALPHA * v;
            }
            C[(size_t)gm * N + gn] = v;
        }
    }
}

// ------------- codebook prep: transpose + squared norms + zero loss ---------
__global__ __launch_bounds__(256) void vq_pre_kernel(const float* __restrict__ emb)
{
    const int j = blockIdx.x;      // code index 0..1023
    const int tid = threadIdx.x;   // 256
    __shared__ float red[256];
    float s = 0.f;
    for (int d = tid; d < LATENT; d += 256) {
        float v = emb[(size_t)d * NUM_EMB + j];
        g_embT[(size_t)j * LATENT + d] = v;
        s += v * v;
    }
    red[tid] = s;
    __syncthreads();
    for (int o = 128; o > 0; o >>= 1) {
        if (tid < o) red[tid] += red[tid + o];
        __syncthreads();
    }
    if (tid == 0) g_embsq[j] = red[0];
    if (blockIdx.x == 0 && tid == 0) g_loss = 0.f;
}

// ------------- per-row argmin over scores + gather + loss partial -----------
__global__ __launch_bounds__(256) void vq_select_kernel()
{
    const int i = blockIdx.x;      // row 0..BATCH-1
    const int tid = threadIdx.x;   // 256
    __shared__ float sv[256];
    __shared__ int   si[256];

    const float* srow = g_scores + (size_t)i * NUM_EMB;
    float best = 3.4e38f;
    int bidx = NUM_EMB;
    for (int j = tid; j < NUM_EMB; j += 256) {
        float v = srow[j];
        if (v < best) { best = v; bidx = j; }   // strided ascending -> first occurrence kept
    }
    sv[tid] = best; si[tid] = bidx;
    __syncthreads();
    for (int o = 128; o > 0; o >>= 1) {
        if (tid < o) {
            float vo = sv[tid + o]; int io = si[tid + o];
            if (vo < sv[tid] || (vo == sv[tid] && io < si[tid])) {
                sv[tid] = vo; si[tid] = io;
            }
        }
        __syncthreads();
    }
    const int j = si[0];   // winning code (first-occurrence tie break, matches jnp.argmin)

    const float* e  = g_embT + (size_t)j * LATENT;
    const float* zr = g_z    + (size_t)i * LATENT;
    float ls = 0.f;
    for (int d = tid; d < LATENT; d += 256) {
        float q = e[d];
        g_q[(size_t)i * LATENT + d] = q;
        float df = q - zr[d];
        ls += df * df;
    }
    __syncthreads();   // all reads of si[0] done before sv reuse
    sv[tid] = ls;
    __syncthreads();
    for (int o = 128; o > 0; o >>= 1) {
        if (tid < o) sv[tid] += sv[tid + o];
        __syncthreads();
    }
    if (tid == 0) atomicAdd(&g_loss, sv[0]);
}

// ------------- finalize: vq_loss = 1.25 * mean((q-z)^2) ---------------------
__global__ void finalize_kernel(float* __restrict__ out, long long pos)
{
    out[pos] = 1.25f * g_loss / (float)((long long)BATCH * LATENT);
}

// ---------------------------------------------------------------------------
extern "C" void kernel_launch(void* const* d_in, const int* in_sizes, int n_in,
                              void* d_out, int out_size)
{
    const float* x   = (const float*)d_in[0];
    const float* W1  = (const float*)d_in[1];
    const float* b1  = (const float*)d_in[2];
    const float* W2  = (const float*)d_in[3];
    const float* b2  = (const float*)d_in[4];
    const float* emb = (const float*)d_in[5];
    const float* W3  = (const float*)d_in[6];
    const float* b3  = (const float*)d_in[7];
    const float* W4  = (const float*)d_in[8];
    const float* b4  = (const float*)d_in[9];
    float* out = (float*)d_out;

    float* h  = nullptr; float* z = nullptr; float* sc = nullptr; float* q = nullptr;
    cudaGetSymbolAddress((void**)&h,  g_h);
    cudaGetSymbolAddress((void**)&z,  g_z);
    cudaGetSymbolAddress((void**)&sc, g_scores);
    cudaGetSymbolAddress((void**)&q,  g_q);
    float* embsq = nullptr;
    cudaGetSymbolAddress((void**)&embsq, g_embsq);

    const dim3 blk(256);

    // 0. codebook prep (transpose + norms + zero loss accumulator)
    vq_pre_kernel<<<NUM_EMB, blk>>>(emb);

    // 1. h = leaky_relu(x @ W1 + b1)       [16384,2048] K=700
    gemm_kernel<1><<<dim3((H_ENC + BN - 1) / BN, BATCH / BM), blk>>>(x, W1, b1, h, BATCH, H_ENC, IN_DIM);

    // 2. z = h @ W2 + b2                   [16384,512]  K=2048
    gemm_kernel<0><<<dim3((LATENT + BN - 1) / BN, BATCH / BM), blk>>>(h, W2, b2, z, BATCH, LATENT, H_ENC);

    // 3. scores = -2*(z @ emb) + |e|^2     [16384,1024] K=512
    gemm_kernel<2><<<dim3((NUM_EMB + BN - 1) / BN, BATCH / BM), blk>>>(z, emb, embsq, sc, BATCH, NUM_EMB, LATENT);

    // 4. argmin + gather quantized + loss partials
    vq_select_kernel<<<BATCH, blk>>>();

    // 5. h2 = leaky_relu(q @ W3 + b3)      [16384,2048] K=512  (reuse g_h)
    gemm_kernel<1><<<dim3((H_DEC + BN - 1) / BN, BATCH / BM), blk>>>(q, W3, b3, h, BATCH, H_DEC, LATENT);

    // 6. recon = h2 @ W4 + b4 -> d_out     [16384,700]  K=2048
    gemm_kernel<0><<<dim3((OUT_DIM + BN - 1) / BN, BATCH / BM), blk>>>(h, W4, b4, out, BATCH, OUT_DIM, H_DEC);

    // 7. vq_loss scalar at the tail of the output buffer
    finalize_kernel<<<1, 1>>>(out, (long long)out_size - 1);
}

// round 7
// speedup vs baseline: 2.6066x; 2.6066x over previous
#include <cuda_runtime.h>
#include <cuda_bf16.h>
#include <cstdint>

#define BATCH   16384
#define IN_DIM  700
#define H_ENC   2048
#define LATENT  512
#define H_DEC   2048
#define OUT_DIM 700
#define NUM_EMB 1024
#define ALPHA   0.2f

#define KP1 704   // IN_DIM padded to multiple of 32
#define NB4 768   // OUT_DIM padded to multiple of 128 (B rows of last GEMM)

// ---------------- scratch (static __device__, no runtime allocation) --------
__device__ __align__(128) __nv_bfloat16 g_xh[BATCH * KP1];
__device__ __align__(128) __nv_bfloat16 g_xm[BATCH * KP1];
__device__ __align__(128) __nv_bfloat16 g_hh[BATCH * H_ENC];
__device__ __align__(128) __nv_bfloat16 g_hm[BATCH * H_ENC];
__device__ __align__(128) float g_z[BATCH * LATENT];
__device__ __align__(128) __nv_bfloat16 g_zh[BATCH * LATENT];
__device__ __align__(128) __nv_bfloat16 g_zm[BATCH * LATENT];
__device__ __align__(128) float g_scores[BATCH * NUM_EMB];
__device__ __align__(128) __nv_bfloat16 g_qh[BATCH * LATENT];
__device__ __align__(128) __nv_bfloat16 g_qm[BATCH * LATENT];
__device__ __align__(128) float g_embT[NUM_EMB * LATENT];
__device__ __align__(128) __nv_bfloat16 g_ebh[NUM_EMB * LATENT];
__device__ __align__(128) __nv_bfloat16 g_ebm[NUM_EMB * LATENT];
__device__ float g_embsq[NUM_EMB];
__device__ float g_loss;
__device__ __align__(128) __nv_bfloat16 g_w1h[H_ENC * KP1];
__device__ __align__(128) __nv_bfloat16 g_w1m[H_ENC * KP1];
__device__ __align__(128) __nv_bfloat16 g_w2h[LATENT * H_ENC];
__device__ __align__(128) __nv_bfloat16 g_w2m[LATENT * H_ENC];
__device__ __align__(128) __nv_bfloat16 g_w3h[H_DEC * LATENT];
__device__ __align__(128) __nv_bfloat16 g_w3m[H_DEC * LATENT];
__device__ __align__(128) __nv_bfloat16 g_w4h[NB4 * H_DEC];
__device__ __align__(128) __nv_bfloat16 g_w4m[NB4 * H_DEC];

// ======================= helpers ===========================================
__device__ __forceinline__ uint32_t smem_u32(const void* p) {
    uint32_t a;
    asm("{ .reg .u64 t; cvta.to.shared.u64 t, %1; cvt.u32.u64 %0, t; }"
        : "=r"(a) : "l"(p));
    return a;
}
__device__ __forceinline__ uint32_t lds32(uint32_t a) {
    uint32_t v;
    asm volatile("ld.shared.b32 %0, [%1];" : "=r"(v) : "r"(a));
    return v;
}
#define CP16(dst, src) \
    asm volatile("cp.async.cg.shared.global [%0], [%1], 16;" :: "r"(dst), "l"(src))
#define CP_COMMIT() asm volatile("cp.async.commit_group;")
#define CP_WAIT2()  asm volatile("cp.async.wait_group 2;")

__device__ __forceinline__ void mma16816(float* c, const uint32_t* a, const uint32_t* b) {
    asm volatile(
        "mma.sync.aligned.m16n8k16.row.col.f32.bf16.bf16.f32 "
        "{%0,%1,%2,%3}, {%4,%5,%6,%7}, {%8,%9}, {%0,%1,%2,%3};"
        : "+f"(c[0]), "+f"(c[1]), "+f"(c[2]), "+f"(c[3])
        : "r"(a[0]), "r"(a[1]), "r"(a[2]), "r"(a[3]), "r"(b[0]), "r"(b[1]));
}

__device__ __forceinline__ void splitf(float v, __nv_bfloat16& h, __nv_bfloat16& m) {
    h = __float2bfloat16(v);
    m = __float2bfloat16(v - __bfloat162float(h));
}

// smem tile layout: [128 rows][32 bf16], 64B/row, 16B chunks XOR-swizzled:
// byte = r*64 + ((ck ^ ((r>>1)&3))<<4) + inner
__device__ __forceinline__ uint32_t tile_addr(uint32_t base, int r, int ck, int b) {
    return base + r * 64 + (((uint32_t)(ck ^ ((r >> 1) & 3))) << 4) + b;
}

// ===================== bf16x2-split tensor-core GEMM ========================
// C[M,N] = epi( A[M,Kp] @ B[NB,Kp]^T ), A = Ah+Am, B = Bh+Bm (bf16 pairs)
// EPI 0: leaky(acc+bias) -> bf16 hi/mid
// EPI 1: acc+bias        -> fp32 + bf16 hi/mid
// EPI 2: -2*acc+bias     -> fp32
// EPI 3: acc+bias        -> fp32 (ragged N guard)
#define STAGES 4
#define STAGE_BYTES 32768
#define SMEM_BYTES (STAGES * STAGE_BYTES)

template <int EPI>
__global__ __launch_bounds__(256, 1) void tc_gemm(
    const __nv_bfloat16* __restrict__ Ah, const __nv_bfloat16* __restrict__ Am,
    const __nv_bfloat16* __restrict__ Bh, const __nv_bfloat16* __restrict__ Bm,
    const float* __restrict__ bias, float* __restrict__ Cf,
    __nv_bfloat16* __restrict__ Ch, __nv_bfloat16* __restrict__ Cm,
    int N, int Kp)
{
    extern __shared__ char smem[];
    const uint32_t sb = smem_u32(smem);
    const int tid = threadIdx.x;
    const int wid = tid >> 5, lane = tid & 31;
    const int g = lane >> 2, tg = lane & 3;
    const int wm = (wid >> 2) * 64;    // warp m offset (0/64)
    const int wn = (wid & 3) * 32;     // warp n offset (0/32/64/96)
    const int m0 = blockIdx.y * 128, n0 = blockIdx.x * 128;
    const int nch = Kp >> 5;

    float acc[4][4][4];
#pragma unroll
    for (int i = 0; i < 4; i++)
#pragma unroll
        for (int j = 0; j < 4; j++)
#pragma unroll
            for (int k = 0; k < 4; k++) acc[i][j][k] = 0.f;

    // ---- async stage loader: 8 x 16B per thread per stage ----
    auto load_stage = [&](int buf, int ch) {
        const int k0 = ch * 32;
#pragma unroll
        for (int i = 0; i < 2; i++) {
            const int id = i * 256 + tid;
            const int r = id >> 2, ck = id & 3;
            const uint32_t dst = tile_addr(sb + buf * STAGE_BYTES, r, ck, 0);
            const size_t ao = (size_t)(m0 + r) * Kp + k0 + ck * 8;
            const size_t bo = (size_t)(n0 + r) * Kp + k0 + ck * 8;
            CP16(dst,          Ah + ao);
            CP16(dst + 8192,   Am + ao);
            CP16(dst + 16384,  Bh + bo);
            CP16(dst + 24576,  Bm + bo);
        }
    };

    auto compute = [&](int buf) {
        const uint32_t ba = sb + buf * STAGE_BYTES;
#pragma unroll
        for (int ks = 0; ks < 2; ks++) {
            uint32_t ah[4][4], am[4][4], bh[4][2], bm[4][2];
#pragma unroll
            for (int mt = 0; mt < 4; mt++) {
                const int r0 = wm + mt * 16 + g, r1 = r0 + 8;
                ah[mt][0] = lds32(tile_addr(ba,        r0, 2 * ks,     tg * 4));
                ah[mt][1] = lds32(tile_addr(ba,        r1, 2 * ks,     tg * 4));
                ah[mt][2] = lds32(tile_addr(ba,        r0, 2 * ks + 1, tg * 4));
                ah[mt][3] = lds32(tile_addr(ba,        r1, 2 * ks + 1, tg * 4));
                am[mt][0] = lds32(tile_addr(ba + 8192, r0, 2 * ks,     tg * 4));
                am[mt][1] = lds32(tile_addr(ba + 8192, r1, 2 * ks,     tg * 4));
                am[mt][2] = lds32(tile_addr(ba + 8192, r0, 2 * ks + 1, tg * 4));
                am[mt][3] = lds32(tile_addr(ba + 8192, r1, 2 * ks + 1, tg * 4));
            }
#pragma unroll
            for (int nt = 0; nt < 4; nt++) {
                const int rn = wn + nt * 8 + g;
                bh[nt][0] = lds32(tile_addr(ba + 16384, rn, 2 * ks,     tg * 4));
                bh[nt][1] = lds32(tile_addr(ba + 16384, rn, 2 * ks + 1, tg * 4));
                bm[nt][0] = lds32(tile_addr(ba + 24576, rn, 2 * ks,     tg * 4));
                bm[nt][1] = lds32(tile_addr(ba + 24576, rn, 2 * ks + 1, tg * 4));
            }
#pragma unroll
            for (int mt = 0; mt < 4; mt++)
#pragma unroll
                for (int nt = 0; nt < 4; nt++) {
                    mma16816(acc[mt][nt], ah[mt], bh[nt]);
                    mma16816(acc[mt][nt], ah[mt], bm[nt]);
                    mma16816(acc[mt][nt], am[mt], bh[nt]);
                }
        }
    };

    // ---- prologue: 3 stages in flight ----
#pragma unroll
    for (int s = 0; s < 3; s++) {
        if (s < nch) load_stage(s, s);
        CP_COMMIT();
    }

    // ---- main loop ----
    for (int c = 0; c < nch; c++) {
        CP_WAIT2();
        __syncthreads();
        const int nxt = c + 3;
        if (nxt < nch) load_stage(nxt & 3, nxt);
        CP_COMMIT();
        compute(c & 3);
    }

    // ---- epilogue ----
#pragma unroll
    for (int mt = 0; mt < 4; mt++)
#pragma unroll
        for (int nt = 0; nt < 4; nt++) {
            const int gn = n0 + wn + nt * 8 + tg * 2;
#pragma unroll
            for (int hh = 0; hh < 2; hh++) {
                const int gm = m0 + wm + mt * 16 + g + hh * 8;
                float v0 = acc[mt][nt][hh * 2 + 0];
                float v1 = acc[mt][nt][hh * 2 + 1];
                if (EPI == 2) {
                    v0 = -2.f * v0 + bias[gn];
                    v1 = -2.f * v1 + bias[gn + 1];
                } else {
                    v0 += bias[gn];
                    v1 += bias[gn + 1];
                    if (EPI == 0) {
                        v0 = (v0 >= 0.f) ? v0 : ALPHA * v0;
                        v1 = (v1 >= 0.f) ? v1 : ALPHA * v1;
                    }
                }
                if (EPI == 0 || EPI == 1) {
                    __nv_bfloat16 h0, m0b, h1, m1b;
                    splitf(v0, h0, m0b);
                    splitf(v1, h1, m1b);
                    __nv_bfloat162 hp; hp.x = h0; hp.y = h1;
                    __nv_bfloat162 mp; mp.x = m0b; mp.y = m1b;
                    *reinterpret_cast<__nv_bfloat162*>(Ch + (size_t)gm * N + gn) = hp;
                    *reinterpret_cast<__nv_bfloat162*>(Cm + (size_t)gm * N + gn) = mp;
                }
                if (EPI == 1 || EPI == 2) {
                    *reinterpret_cast<float2*>(Cf + (size_t)gm * N + gn) = make_float2(v0, v1);
                }
                if (EPI == 3) {
                    if (gn < N)
                        *reinterpret_cast<float2*>(Cf + (size_t)gm * N + gn) = make_float2(v0, v1);
                }
            }
        }
}

// ------------- x -> bf16 hi/mid with K padding ------------------------------
__global__ __launch_bounds__(256) void conv_x(const float* __restrict__ x)
{
    int i = blockIdx.x * 256 + threadIdx.x;
    if (i >= BATCH * KP1) return;
    int row = i / KP1, col = i - row * KP1;
    float v = (col < IN_DIM) ? x[(size_t)row * IN_DIM + col] : 0.f;
    __nv_bfloat16 h, m;
    splitf(v, h, m);
    g_xh[i] = h; g_xm[i] = m;
}

// ------------- weight transpose + split + pad: in[K][N] -> out[Nr][Kp] ------
// grid: x covers Nr/32 blocks, y covers Kp/32 blocks  (FIXED axis order)
__global__ __launch_bounds__(256) void conv_wt(
    const float* __restrict__ in, __nv_bfloat16* __restrict__ oh,
    __nv_bfloat16* __restrict__ om, int K, int N, int Kp, int Nr)
{
    __shared__ float t[32][33];
    const int kb = blockIdx.y * 32, nb = blockIdx.x * 32;
    const int x = threadIdx.x & 31, y4 = (threadIdx.x >> 5) * 4;
#pragma unroll
    for (int i = 0; i < 4; i++) {
        int k = kb + y4 + i, n = nb + x;
        t[y4 + i][x] = (k < K && n < N) ? in[(size_t)k * N + n] : 0.f;
    }
    __syncthreads();
#pragma unroll
    for (int i = 0; i < 4; i++) {
        int n = nb + y4 + i, k = kb + x;
        if (n < Nr && k < Kp) {
            __nv_bfloat16 h, m;
            splitf(t[x][y4 + i], h, m);
            oh[(size_t)n * Kp + k] = h;
            om[(size_t)n * Kp + k] = m;
        }
    }
}

// ------------- codebook prep: transpose + split + norms + zero loss ---------
__global__ __launch_bounds__(256) void vq_pre_kernel(const float* __restrict__ emb)
{
    const int j = blockIdx.x;
    const int tid = threadIdx.x;
    __shared__ float red[256];
    float s = 0.f;
    for (int d = tid; d < LATENT; d += 256) {
        float v = emb[(size_t)d * NUM_EMB + j];
        g_embT[(size_t)j * LATENT + d] = v;
        __nv_bfloat16 h, m;
        splitf(v, h, m);
        g_ebh[(size_t)j * LATENT + d] = h;
        g_ebm[(size_t)j * LATENT + d] = m;
        s += v * v;
    }
    red[tid] = s;
    __syncthreads();
    for (int o = 128; o > 0; o >>= 1) {
        if (tid < o) red[tid] += red[tid + o];
        __syncthreads();
    }
    if (tid == 0) g_embsq[j] = red[0];
    if (blockIdx.x == 0 && tid == 0) g_loss = 0.f;
}

// ------------- per-row argmin + gather (as bf16 pair) + loss partial --------
__global__ __launch_bounds__(256) void vq_select_kernel()
{
    const int i = blockIdx.x;
    const int tid = threadIdx.x;
    __shared__ float sv[256];
    __shared__ int   si[256];

    const float* srow = g_scores + (size_t)i * NUM_EMB;
    float best = 3.4e38f;
    int bidx = NUM_EMB;
    for (int j = tid; j < NUM_EMB; j += 256) {
        float v = srow[j];
        if (v < best) { best = v; bidx = j; }
    }
    sv[tid] = best; si[tid] = bidx;
    __syncthreads();
    for (int o = 128; o > 0; o >>= 1) {
        if (tid < o) {
            float vo = sv[tid + o]; int io = si[tid + o];
            if (vo < sv[tid] || (vo == sv[tid] && io < si[tid])) {
                sv[tid] = vo; si[tid] = io;
            }
        }
        __syncthreads();
    }
    const int j = si[0];

    const float* e  = g_embT + (size_t)j * LATENT;
    const float* zr = g_z    + (size_t)i * LATENT;
    float ls = 0.f;
    for (int d = tid; d < LATENT; d += 256) {
        float q = e[d];
        __nv_bfloat16 h, m;
        splitf(q, h, m);
        g_qh[(size_t)i * LATENT + d] = h;
        g_qm[(size_t)i * LATENT + d] = m;
        float df = q - zr[d];
        ls += df * df;
    }
    __syncthreads();
    sv[tid] = ls;
    __syncthreads();
    for (int o = 128; o > 0; o >>= 1) {
        if (tid < o) sv[tid] += sv[tid + o];
        __syncthreads();
    }
    if (tid == 0) atomicAdd(&g_loss, sv[0]);
}

__global__ void finalize_kernel(float* __restrict__ out, long long pos)
{
    out[pos] = 1.25f * g_loss / (float)((long long)BATCH * LATENT);
}

// ---------------------------------------------------------------------------
extern "C" void kernel_launch(void* const* d_in, const int* in_sizes, int n_in,
                              void* d_out, int out_size)
{
    const float* x   = (const float*)d_in[0];
    const float* W1  = (const float*)d_in[1];
    const float* b1  = (const float*)d_in[2];
    const float* W2  = (const float*)d_in[3];
    const float* b2  = (const float*)d_in[4];
    const float* emb = (const float*)d_in[5];
    const float* W3  = (const float*)d_in[6];
    const float* b3  = (const float*)d_in[7];
    const float* W4  = (const float*)d_in[8];
    const float* b4  = (const float*)d_in[9];
    float* out = (float*)d_out;

    __nv_bfloat16 *xh, *xm, *hh, *hm, *zh, *zm, *qh, *qm, *ebh, *ebm;
    __nv_bfloat16 *w1h, *w1m, *w2h, *w2m, *w3h, *w3m, *w4h, *w4m;
    float *z, *sc, *embsq;
    cudaGetSymbolAddress((void**)&xh,  g_xh);  cudaGetSymbolAddress((void**)&xm,  g_xm);
    cudaGetSymbolAddress((void**)&hh,  g_hh);  cudaGetSymbolAddress((void**)&hm,  g_hm);
    cudaGetSymbolAddress((void**)&zh,  g_zh);  cudaGetSymbolAddress((void**)&zm,  g_zm);
    cudaGetSymbolAddress((void**)&qh,  g_qh);  cudaGetSymbolAddress((void**)&qm,  g_qm);
    cudaGetSymbolAddress((void**)&ebh, g_ebh); cudaGetSymbolAddress((void**)&ebm, g_ebm);
    cudaGetSymbolAddress((void**)&w1h, g_w1h); cudaGetSymbolAddress((void**)&w1m, g_w1m);
    cudaGetSymbolAddress((void**)&w2h, g_w2h); cudaGetSymbolAddress((void**)&w2m, g_w2m);
    cudaGetSymbolAddress((void**)&w3h, g_w3h); cudaGetSymbolAddress((void**)&w3m, g_w3m);
    cudaGetSymbolAddress((void**)&w4h, g_w4h); cudaGetSymbolAddress((void**)&w4m, g_w4m);
    cudaGetSymbolAddress((void**)&z,   g_z);
    cudaGetSymbolAddress((void**)&sc,  g_scores);
    cudaGetSymbolAddress((void**)&embsq, g_embsq);

    cudaFuncSetAttribute(tc_gemm<0>, cudaFuncAttributeMaxDynamicSharedMemorySize, SMEM_BYTES);
    cudaFuncSetAttribute(tc_gemm<1>, cudaFuncAttributeMaxDynamicSharedMemorySize, SMEM_BYTES);
    cudaFuncSetAttribute(tc_gemm<2>, cudaFuncAttributeMaxDynamicSharedMemorySize, SMEM_BYTES);
    cudaFuncSetAttribute(tc_gemm<3>, cudaFuncAttributeMaxDynamicSharedMemorySize, SMEM_BYTES);

    const dim3 blk(256);

    // 0. conversions / prep  (grid = (Nr/32, Kp/32) — matches conv_wt axes)
    conv_x<<<(BATCH * KP1 + 255) / 256, blk>>>(x);
    conv_wt<<<dim3(H_ENC / 32,  KP1 / 32),   blk>>>(W1, w1h, w1m, IN_DIM, H_ENC,  KP1,   H_ENC);
    conv_wt<<<dim3(LATENT / 32, H_ENC / 32), blk>>>(W2, w2h, w2m, H_ENC,  LATENT, H_ENC, LATENT);
    conv_wt<<<dim3(H_DEC / 32,  LATENT / 32),blk>>>(W3, w3h, w3m, LATENT, H_DEC,  LATENT,H_DEC);
    conv_wt<<<dim3(NB4 / 32,    H_DEC / 32), blk>>>(W4, w4h, w4m, H_DEC,  OUT_DIM,H_DEC, NB4);
    vq_pre_kernel<<<NUM_EMB, blk>>>(emb);

    // 1. h = leaky(x @ W1 + b1)  -> bf16 pair
    tc_gemm<0><<<dim3(H_ENC / 128, BATCH / 128), blk, SMEM_BYTES>>>(
        xh, xm, w1h, w1m, b1, nullptr, hh, hm, H_ENC, KP1);
    // 2. z = h @ W2 + b2  -> fp32 + bf16 pair
    tc_gemm<1><<<dim3(LATENT / 128, BATCH / 128), blk, SMEM_BYTES>>>(
        hh, hm, w2h, w2m, b2, z, zh, zm, LATENT, H_ENC);
    // 3. scores = -2*(z @ emb) + |e|^2  -> fp32
    tc_gemm<2><<<dim3(NUM_EMB / 128, BATCH / 128), blk, SMEM_BYTES>>>(
        zh, zm, ebh, ebm, embsq, sc, nullptr, nullptr, NUM_EMB, LATENT);
    // 4. argmin + gather + loss
    vq_select_kernel<<<BATCH, blk>>>();
    // 5. h2 = leaky(q @ W3 + b3)  -> bf16 pair (reuse h buffers)
    tc_gemm<0><<<dim3(H_DEC / 128, BATCH / 128), blk, SMEM_BYTES>>>(
        qh, qm, w3h, w3m, b3, nullptr, hh, hm, H_DEC, LATENT);
    // 6. recon = h2 @ W4 + b4 -> fp32 out (ragged N=700)
    tc_gemm<3><<<dim3((OUT_DIM + 127) / 128, BATCH / 128), blk, SMEM_BYTES>>>(
        hh, hm, w4h, w4m, b4, out, nullptr, nullptr, OUT_DIM, H_DEC);
    // 7. scalar loss
    finalize_kernel<<<1, 1>>>(out, (long long)out_size - 1);
}

// round 8
// speedup vs baseline: 3.1082x; 1.1924x over previous
#include <cuda_runtime.h>
#include <cuda_fp16.h>
#include <cstdint>

#define BATCH   16384
#define IN_DIM  700
#define H_ENC   2048
#define LATENT  512
#define H_DEC   2048
#define OUT_DIM 700
#define NUM_EMB 1024
#define ALPHA   0.2f

#define KP1 704   // IN_DIM padded to multiple of 32
#define NB4 768   // OUT_DIM padded to multiple of 128

// ---------------- scratch (static __device__, no runtime allocation) --------
__device__ __align__(128) __half g_xh[BATCH * KP1];
__device__ __align__(128) __half g_xm[BATCH * KP1];
__device__ __align__(128) __half g_hh[BATCH * H_ENC];
__device__ __align__(128) __half g_hm[BATCH * H_ENC];
__device__ __align__(128) float  g_z[BATCH * LATENT];
__device__ __align__(128) __half g_zh[BATCH * LATENT];
__device__ __align__(128) __half g_zm[BATCH * LATENT];
__device__ __align__(128) __half g_qh[BATCH * LATENT];
__device__ __align__(128) __half g_qm[BATCH * LATENT];
__device__ __align__(128) float  g_embT[NUM_EMB * LATENT];
__device__ __align__(128) __half g_ebh[NUM_EMB * LATENT];
__device__ __align__(128) __half g_ebm[NUM_EMB * LATENT];
__device__ float g_embsq[NUM_EMB];
__device__ float g_loss;
__device__ __align__(128) float g_cval[BATCH * 8];   // per-row per-nblock argmin candidates
__device__ __align__(128) int   g_cidx[BATCH * 8];
__device__ __align__(128) __half g_w1h[H_ENC * KP1];
__device__ __align__(128) __half g_w1m[H_ENC * KP1];
__device__ __align__(128) __half g_w2h[LATENT * H_ENC];
__device__ __align__(128) __half g_w2m[LATENT * H_ENC];
__device__ __align__(128) __half g_w3h[H_DEC * LATENT];
__device__ __align__(128) __half g_w3m[H_DEC * LATENT];
__device__ __align__(128) __half g_w4h[NB4 * H_DEC];
__device__ __align__(128) __half g_w4m[NB4 * H_DEC];

// ======================= helpers ===========================================
__device__ __forceinline__ uint32_t smem_u32(const void* p) {
    uint32_t a;
    asm("{ .reg .u64 t; cvta.to.shared.u64 t, %1; cvt.u32.u64 %0, t; }"
        : "=r"(a) : "l"(p));
    return a;
}
#define CP16(dst, src) \
    asm volatile("cp.async.cg.shared.global [%0], [%1], 16;" :: "r"(dst), "l"(src))
#define CP_COMMIT() asm volatile("cp.async.commit_group;")
#define CP_WAIT2()  asm volatile("cp.async.wait_group 2;")

#define LDSM4(r0, r1, r2, r3, a) \
    asm volatile("ldmatrix.sync.aligned.m8n8.x4.shared.b16 {%0,%1,%2,%3}, [%4];" \
        : "=r"(r0), "=r"(r1), "=r"(r2), "=r"(r3) : "r"(a))

__device__ __forceinline__ void mma16816(float* c, const uint32_t* a, const uint32_t* b) {
    asm volatile(
        "mma.sync.aligned.m16n8k16.row.col.f32.f16.f16.f32 "
        "{%0,%1,%2,%3}, {%4,%5,%6,%7}, {%8,%9}, {%0,%1,%2,%3};"
        : "+f"(c[0]), "+f"(c[1]), "+f"(c[2]), "+f"(c[3])
        : "r"(a[0]), "r"(a[1]), "r"(a[2]), "r"(a[3]), "r"(b[0]), "r"(b[1]));
}

__device__ __forceinline__ void splitf(float v, __half& h, __half& m) {
    h = __float2half_rn(v);
    m = __float2half_rn(v - __half2float(h));
}

// smem tile: [128 rows][32 fp16], 64B/row, 16B chunks XOR-swizzled
__device__ __forceinline__ uint32_t tile_addr(uint32_t base, int r, int ck) {
    return base + r * 64 + (((uint32_t)(ck ^ ((r >> 1) & 3))) << 4);
}

// ===================== fp16-split tensor-core GEMM ==========================
// C[M,N] = epi( A[M,Kp] @ B[NB,Kp]^T )
// BS=2: 3 MMAs (ah*bh + ah*bm + am*bh)   BS=1: 2 MMAs (ah*b + am*b)
// EPI 0: leaky(acc+bias) -> half hi/mid
// EPI 1: acc+bias        -> fp32 + half hi/mid
// EPI 2: VQ: per-row argmin of -2*acc+embsq[n] -> block candidates (no C)
// EPI 3: acc+bias        -> fp32 (ragged N guard)
template <int EPI, int BS>
__global__ __launch_bounds__(256, 1) void tc_gemm(
    const __half* __restrict__ Ah, const __half* __restrict__ Am,
    const __half* __restrict__ Bh, const __half* __restrict__ Bm,
    const float* __restrict__ bias, float* __restrict__ Cf,
    __half* __restrict__ Ch, __half* __restrict__ Cm,
    int N, int Kp)
{
    constexpr int STAGE_B = (BS == 2) ? 32768 : 24576;
    extern __shared__ char smem[];
    const uint32_t sb = smem_u32(smem);
    const int tid = threadIdx.x;
    const int wid = tid >> 5, lane = tid & 31;
    const int g = lane >> 2, tg = lane & 3;
    const int wm = (wid >> 2) * 64;
    const int wn = (wid & 3) * 32;
    const int m0 = blockIdx.y * 128, n0 = blockIdx.x * 128;
    const int nch = Kp >> 5;

    float acc[4][4][4];
#pragma unroll
    for (int i = 0; i < 4; i++)
#pragma unroll
        for (int j = 0; j < 4; j++)
#pragma unroll
            for (int k = 0; k < 4; k++) acc[i][j][k] = 0.f;

    auto load_stage = [&](int buf, int ch) {
        const int k0 = ch * 32;
#pragma unroll
        for (int i = 0; i < 2; i++) {
            const int id = i * 256 + tid;
            const int r = id >> 2, ck = id & 3;
            const uint32_t dst = tile_addr(sb + buf * STAGE_B, r, ck);
            const size_t ao = (size_t)(m0 + r) * Kp + k0 + ck * 8;
            const size_t bo = (size_t)(n0 + r) * Kp + k0 + ck * 8;
            CP16(dst,         Ah + ao);
            CP16(dst + 8192,  Am + ao);
            CP16(dst + 16384, Bh + bo);
            if (BS == 2) CP16(dst + 24576, Bm + bo);
        }
    };

    auto compute = [&](int buf) {
        const uint32_t ba = sb + buf * STAGE_B;
        const int rA = wm + (lane & 15), cA = lane >> 4;
        const int rB = wn + (lane & 7) + ((lane >> 4) << 3), cB = (lane >> 3) & 1;
        uint32_t aA[2], aB[2];
        aA[0] = tile_addr(ba, rA, cA);
        aA[1] = tile_addr(ba, rA, cA + 2);
        aB[0] = tile_addr(ba + 16384, rB, cB);
        aB[1] = tile_addr(ba + 16384, rB, cB + 2);
#pragma unroll
        for (int ks = 0; ks < 2; ks++) {
            uint32_t ah[4][4], am[4][4], bh[4][2], bm[4][2];
#pragma unroll
            for (int mt = 0; mt < 4; mt++) {
                LDSM4(ah[mt][0], ah[mt][1], ah[mt][2], ah[mt][3], aA[ks] + mt * 1024);
                LDSM4(am[mt][0], am[mt][1], am[mt][2], am[mt][3], aA[ks] + 8192 + mt * 1024);
            }
#pragma unroll
            for (int p = 0; p < 2; p++) {
                LDSM4(bh[2*p][0], bh[2*p][1], bh[2*p+1][0], bh[2*p+1][1], aB[ks] + p * 1024);
                if (BS == 2)
                    LDSM4(bm[2*p][0], bm[2*p][1], bm[2*p+1][0], bm[2*p+1][1],
                          aB[ks] + 8192 + p * 1024);
            }
#pragma unroll
            for (int mt = 0; mt < 4; mt++)
#pragma unroll
                for (int nt = 0; nt < 4; nt++) {
                    mma16816(acc[mt][nt], ah[mt], bh[nt]);
                    if (BS == 2) {
                        mma16816(acc[mt][nt], ah[mt], bm[nt]);
                        mma16816(acc[mt][nt], am[mt], bh[nt]);
                    } else {
                        mma16816(acc[mt][nt], am[mt], bh[nt]);
                    }
                }
        }
    };

    // prologue: 3 stages in flight
#pragma unroll
    for (int s = 0; s < 3; s++) {
        if (s < nch) load_stage(s, s);
        CP_COMMIT();
    }
    // main loop
    for (int c = 0; c < nch; c++) {
        CP_WAIT2();
        __syncthreads();
        const int nxt = c + 3;
        if (nxt < nch) load_stage(nxt & 3, nxt);
        CP_COMMIT();
        compute(c & 3);
    }

    if (EPI == 2) {
        // ---- fused per-row argmin over this 128-col block ----
        __syncthreads();                       // all compute done; reuse smem
        float* sval = reinterpret_cast<float*>(smem);
        int*   sidx = reinterpret_cast<int*>(smem + 2048);
#pragma unroll
        for (int mt = 0; mt < 4; mt++)
#pragma unroll
            for (int hh = 0; hh < 2; hh++) {
                float bv = 3.4e38f; int bi = 0x7FFFFFFF;
#pragma unroll
                for (int nt = 0; nt < 4; nt++)
#pragma unroll
                    for (int j = 0; j < 2; j++) {
                        const int gn = n0 + wn + nt * 8 + tg * 2 + j;
                        float s = -2.f * acc[mt][nt][hh * 2 + j] + bias[gn];
                        if (s < bv || (s == bv && gn < bi)) { bv = s; bi = gn; }
                    }
#pragma unroll
                for (int o = 1; o < 4; o <<= 1) {
                    float ov = __shfl_xor_sync(0xFFFFFFFF, bv, o);
                    int   oi = __shfl_xor_sync(0xFFFFFFFF, bi, o);
                    if (ov < bv || (ov == bv && oi < bi)) { bv = ov; bi = oi; }
                }
                const int lr = wm + mt * 16 + hh * 8 + g;
                if (tg == 0) { sval[lr * 4 + (wid & 3)] = bv; sidx[lr * 4 + (wid & 3)] = bi; }
            }
        __syncthreads();
        if (tid < 128) {
            float bv = sval[tid * 4]; int bi = sidx[tid * 4];
#pragma unroll
            for (int w = 1; w < 4; w++) {
                float ov = sval[tid * 4 + w]; int oi = sidx[tid * 4 + w];
                if (ov < bv || (ov == bv && oi < bi)) { bv = ov; bi = oi; }
            }
            g_cval[(size_t)(m0 + tid) * 8 + blockIdx.x] = bv;
            g_cidx[(size_t)(m0 + tid) * 8 + blockIdx.x] = bi;
        }
        return;
    }

    // ---- standard epilogues ----
#pragma unroll
    for (int mt = 0; mt < 4; mt++)
#pragma unroll
        for (int nt = 0; nt < 4; nt++) {
            const int gn = n0 + wn + nt * 8 + tg * 2;
#pragma unroll
            for (int hh = 0; hh < 2; hh++) {
                const int gm = m0 + wm + mt * 16 + g + hh * 8;
                float v0 = acc[mt][nt][hh * 2 + 0];
                float v1 = acc[mt][nt][hh * 2 + 1];
                if (EPI == 3) {
                    if (gn < N) {
                        v0 += bias[gn]; v1 += bias[gn + 1];
                        *reinterpret_cast<float2*>(Cf + (size_t)gm * N + gn) = make_float2(v0, v1);
                    }
                } else {
                    v0 += bias[gn]; v1 += bias[gn + 1];
                    if (EPI == 0) {
                        v0 = (v0 >= 0.f) ? v0 : ALPHA * v0;
                        v1 = (v1 >= 0.f) ? v1 : ALPHA * v1;
                    }
                    __half h0, m0h, h1, m1h;
                    splitf(v0, h0, m0h);
                    splitf(v1, h1, m1h);
                    __half2 hp; hp.x = h0; hp.y = h1;
                    __half2 mp; mp.x = m0h; mp.y = m1h;
                    *reinterpret_cast<__half2*>(Ch + (size_t)gm * N + gn) = hp;
                    *reinterpret_cast<__half2*>(Cm + (size_t)gm * N + gn) = mp;
                    if (EPI == 1)
                        *reinterpret_cast<float2*>(Cf + (size_t)gm * N + gn) = make_float2(v0, v1);
                }
            }
        }
}

// ------------- x -> fp16 hi/mid with K padding ------------------------------
__global__ __launch_bounds__(256) void conv_x(const float* __restrict__ x)
{
    int i = blockIdx.x * 256 + threadIdx.x;
    if (i >= BATCH * KP1) return;
    int row = i / KP1, col = i - row * KP1;
    float v = (col < IN_DIM) ? x[(size_t)row * IN_DIM + col] : 0.f;
    __half h, m;
    splitf(v, h, m);
    g_xh[i] = h; g_xm[i] = m;
}

// ------------- weight transpose + split + pad: in[K][N] -> out[Nr][Kp] ------
// grid: (Nr/32, Kp/32)
__global__ __launch_bounds__(256) void conv_wt(
    const float* __restrict__ in, __half* __restrict__ oh,
    __half* __restrict__ om, int K, int N, int Kp, int Nr)
{
    __shared__ float t[32][33];
    const int kb = blockIdx.y * 32, nb = blockIdx.x * 32;
    const int x = threadIdx.x & 31, y4 = (threadIdx.x >> 5) * 4;
#pragma unroll
    for (int i = 0; i < 4; i++) {
        int k = kb + y4 + i, n = nb + x;
        t[y4 + i][x] = (k < K && n < N) ? in[(size_t)k * N + n] : 0.f;
    }
    __syncthreads();
#pragma unroll
    for (int i = 0; i < 4; i++) {
        int n = nb + y4 + i, k = kb + x;
        if (n < Nr && k < Kp) {
            __half h, m;
            splitf(t[x][y4 + i], h, m);
            oh[(size_t)n * Kp + k] = h;
            om[(size_t)n * Kp + k] = m;
        }
    }
}

// ------------- codebook prep: transpose + split + norms + zero loss ---------
__global__ __launch_bounds__(256) void vq_pre_kernel(const float* __restrict__ emb)
{
    const int j = blockIdx.x;
    const int tid = threadIdx.x;
    __shared__ float red[256];
    float s = 0.f;
    for (int d = tid; d < LATENT; d += 256) {
        float v = emb[(size_t)d * NUM_EMB + j];
        g_embT[(size_t)j * LATENT + d] = v;
        __half h, m;
        splitf(v, h, m);
        g_ebh[(size_t)j * LATENT + d] = h;
        g_ebm[(size_t)j * LATENT + d] = m;
        s += v * v;
    }
    red[tid] = s;
    __syncthreads();
    for (int o = 128; o > 0; o >>= 1) {
        if (tid < o) red[tid] += red[tid + o];
        __syncthreads();
    }
    if (tid == 0) g_embsq[j] = red[0];
    if (blockIdx.x == 0 && tid == 0) g_loss = 0.f;
}

// ------------- final argmin over 8 block candidates + gather + loss ---------
__global__ __launch_bounds__(256) void vq_select2()
{
    const int row = blockIdx.x * 8 + (threadIdx.x >> 5);
    const int lane = threadIdx.x & 31;
    float bv = 3.4e38f; int bi = 0x7FFFFFFF;
    if (lane < 8) { bv = g_cval[(size_t)row * 8 + lane]; bi = g_cidx[(size_t)row * 8 + lane]; }
#pragma unroll
    for (int o = 1; o < 8; o <<= 1) {
        float ov = __shfl_xor_sync(0xFFFFFFFF, bv, o);
        int   oi = __shfl_xor_sync(0xFFFFFFFF, bi, o);
        if (ov < bv || (ov == bv && oi < bi)) { bv = ov; bi = oi; }
    }
    const int j = __shfl_sync(0xFFFFFFFF, bi, 0);

    const float* e  = g_embT + (size_t)j * LATENT;
    const float* zr = g_z    + (size_t)row * LATENT;
    float ls = 0.f;
#pragma unroll
    for (int d = lane; d < LATENT; d += 32) {
        float q = e[d];
        __half h, m;
        splitf(q, h, m);
        g_qh[(size_t)row * LATENT + d] = h;
        g_qm[(size_t)row * LATENT + d] = m;
        float df = q - zr[d];
        ls += df * df;
    }
#pragma unroll
    for (int o = 16; o > 0; o >>= 1)
        ls += __shfl_xor_sync(0xFFFFFFFF, ls, o);
    if (lane == 0) atomicAdd(&g_loss, ls);
}

__global__ void finalize_kernel(float* __restrict__ out, long long pos)
{
    out[pos] = 1.25f * g_loss / (float)((long long)BATCH * LATENT);
}

// ---------------------------------------------------------------------------
extern "C" void kernel_launch(void* const* d_in, const int* in_sizes, int n_in,
                              void* d_out, int out_size)
{
    const float* x   = (const float*)d_in[0];
    const float* W1  = (const float*)d_in[1];
    const float* b1  = (const float*)d_in[2];
    const float* W2  = (const float*)d_in[3];
    const float* b2  = (const float*)d_in[4];
    const float* emb = (const float*)d_in[5];
    const float* W3  = (const float*)d_in[6];
    const float* b3  = (const float*)d_in[7];
    const float* W4  = (const float*)d_in[8];
    const float* b4  = (const float*)d_in[9];
    float* out = (float*)d_out;

    __half *xh, *xm, *hh, *hm, *zh, *zm, *qh, *qm, *ebh, *ebm;
    __half *w1h, *w1m, *w2h, *w2m, *w3h, *w3m, *w4h, *w4m;
    float *z, *embsq;
    cudaGetSymbolAddress((void**)&xh,  g_xh);  cudaGetSymbolAddress((void**)&xm,  g_xm);
    cudaGetSymbolAddress((void**)&hh,  g_hh);  cudaGetSymbolAddress((void**)&hm,  g_hm);
    cudaGetSymbolAddress((void**)&zh,  g_zh);  cudaGetSymbolAddress((void**)&zm,  g_zm);
    cudaGetSymbolAddress((void**)&qh,  g_qh);  cudaGetSymbolAddress((void**)&qm,  g_qm);
    cudaGetSymbolAddress((void**)&ebh, g_ebh); cudaGetSymbolAddress((void**)&ebm, g_ebm);
    cudaGetSymbolAddress((void**)&w1h, g_w1h); cudaGetSymbolAddress((void**)&w1m, g_w1m);
    cudaGetSymbolAddress((void**)&w2h, g_w2h); cudaGetSymbolAddress((void**)&w2m, g_w2m);
    cudaGetSymbolAddress((void**)&w3h, g_w3h); cudaGetSymbolAddress((void**)&w3m, g_w3m);
    cudaGetSymbolAddress((void**)&w4h, g_w4h); cudaGetSymbolAddress((void**)&w4m, g_w4m);
    cudaGetSymbolAddress((void**)&z,   g_z);
    cudaGetSymbolAddress((void**)&embsq, g_embsq);

    const int SM2 = 4 * 32768;   // BS=2 stages
    const int SM1 = 4 * 24576;   // BS=1 stages
    cudaFuncSetAttribute((const void*)tc_gemm<0,2>, cudaFuncAttributeMaxDynamicSharedMemorySize, SM2);
    cudaFuncSetAttribute((const void*)tc_gemm<1,2>, cudaFuncAttributeMaxDynamicSharedMemorySize, SM2);
    cudaFuncSetAttribute((const void*)tc_gemm<2,2>, cudaFuncAttributeMaxDynamicSharedMemorySize, SM2);
    cudaFuncSetAttribute((const void*)tc_gemm<0,1>, cudaFuncAttributeMaxDynamicSharedMemorySize, SM1);
    cudaFuncSetAttribute((const void*)tc_gemm<3,1>, cudaFuncAttributeMaxDynamicSharedMemorySize, SM1);

    const dim3 blk(256);

    // 0. conversions / prep
    conv_x<<<(BATCH * KP1 + 255) / 256, blk>>>(x);
    conv_wt<<<dim3(H_ENC / 32,  KP1 / 32),    blk>>>(W1, w1h, w1m, IN_DIM, H_ENC,  KP1,    H_ENC);
    conv_wt<<<dim3(LATENT / 32, H_ENC / 32),  blk>>>(W2, w2h, w2m, H_ENC,  LATENT, H_ENC,  LATENT);
    conv_wt<<<dim3(H_DEC / 32,  LATENT / 32), blk>>>(W3, w3h, w3m, LATENT, H_DEC,  LATENT, H_DEC);
    conv_wt<<<dim3(NB4 / 32,    H_DEC / 32),  blk>>>(W4, w4h, w4m, H_DEC,  OUT_DIM, H_DEC, NB4);
    vq_pre_kernel<<<NUM_EMB, blk>>>(emb);

    // 1. h = leaky(x @ W1 + b1)  -> fp16 pair   (3-MMA path)
    tc_gemm<0,2><<<dim3(H_ENC / 128, BATCH / 128), blk, SM2>>>(
        xh, xm, w1h, w1m, b1, nullptr, hh, hm, H_ENC, KP1);
    // 2. z = h @ W2 + b2  -> fp32 + fp16 pair   (3-MMA path)
    tc_gemm<1,2><<<dim3(LATENT / 128, BATCH / 128), blk, SM2>>>(
        hh, hm, w2h, w2m, b2, z, zh, zm, LATENT, H_ENC);
    // 3. VQ scores + fused per-block argmin     (3-MMA path)
    tc_gemm<2,2><<<dim3(NUM_EMB / 128, BATCH / 128), blk, SM2>>>(
        zh, zm, ebh, ebm, embsq, nullptr, nullptr, nullptr, NUM_EMB, LATENT);
    // 4. final argmin + gather + loss
    vq_select2<<<BATCH / 8, blk>>>();
    // 5. h2 = leaky(q @ W3 + b3)  -> fp16 pair  (2-MMA path, B single fp16)
    tc_gemm<0,1><<<dim3(H_DEC / 128, BATCH / 128), blk, SM1>>>(
        qh, qm, w3h, nullptr, b3, nullptr, hh, hm, H_DEC, LATENT);
    // 6. recon = h2 @ W4 + b4 -> fp32 out       (2-MMA path)
    tc_gemm<3,1><<<dim3((OUT_DIM + 127) / 128, BATCH / 128), blk, SM1>>>(
        hh, hm, w4h, nullptr, b4, out, nullptr, nullptr, OUT_DIM, H_DEC);
    // 7. scalar loss
    finalize_kernel<<<1, 1>>>(out, (long long)out_size - 1);
}

// round 9
// speedup vs baseline: 3.5829x; 1.1527x over previous
#include <cuda_runtime.h>
#include <cuda_fp16.h>
#include <cstdint>

#define BATCH   16384
#define IN_DIM  700
#define H_ENC   2048
#define LATENT  512
#define H_DEC   2048
#define OUT_DIM 700
#define NUM_EMB 1024
#define ALPHA   0.2f

#define KP1 704   // IN_DIM padded to multiple of 32
#define NB4 768   // OUT_DIM padded to multiple of 128

// ---------------- scratch (static __device__, no runtime allocation) --------
__device__ __align__(128) __half g_xh[BATCH * KP1];
__device__ __align__(128) __half g_xm[BATCH * KP1];
__device__ __align__(128) __half g_hh[BATCH * H_ENC];
__device__ __align__(128) __half g_hm[BATCH * H_ENC];
__device__ __align__(128) float  g_z[BATCH * LATENT];
__device__ __align__(128) __half g_zh[BATCH * LATENT];
__device__ __align__(128) __half g_zm[BATCH * LATENT];
__device__ __align__(128) __half g_qh[BATCH * LATENT];
__device__ __align__(128) __half g_qm[BATCH * LATENT];
__device__ __align__(128) float  g_embT[NUM_EMB * LATENT];
__device__ __align__(128) __half g_ebh[NUM_EMB * LATENT];
__device__ __align__(128) __half g_ebm[NUM_EMB * LATENT];
__device__ float g_embsq[NUM_EMB];
__device__ float g_loss;
__device__ __align__(128) float g_cval[BATCH * 8];
__device__ __align__(128) int   g_cidx[BATCH * 8];
__device__ __align__(128) __half g_w1h[H_ENC * KP1];
__device__ __align__(128) __half g_w1m[H_ENC * KP1];
__device__ __align__(128) __half g_w2h[LATENT * H_ENC];
__device__ __align__(128) __half g_w2m[LATENT * H_ENC];
__device__ __align__(128) __half g_w3h[H_DEC * LATENT];
__device__ __align__(128) __half g_w3m[H_DEC * LATENT];
__device__ __align__(128) __half g_w4h[NB4 * H_DEC];
__device__ __align__(128) __half g_w4m[NB4 * H_DEC];

// ======================= helpers ===========================================
__device__ __forceinline__ uint32_t smem_u32(const void* p) {
    uint32_t a;
    asm("{ .reg .u64 t; cvta.to.shared.u64 t, %1; cvt.u32.u64 %0, t; }"
        : "=r"(a) : "l"(p));
    return a;
}
#define CP16(dst, src) \
    asm volatile("cp.async.cg.shared.global [%0], [%1], 16;" :: "r"(dst), "l"(src))
#define CP_COMMIT() asm volatile("cp.async.commit_group;")
#define CP_WAIT1()  asm volatile("cp.async.wait_group 1;")

#define LDSM4(r0, r1, r2, r3, a) \
    asm volatile("ldmatrix.sync.aligned.m8n8.x4.shared.b16 {%0,%1,%2,%3}, [%4];" \
        : "=r"(r0), "=r"(r1), "=r"(r2), "=r"(r3) : "r"(a))

__device__ __forceinline__ void mma16816(float* c, const uint32_t* a, const uint32_t* b) {
    asm volatile(
        "mma.sync.aligned.m16n8k16.row.col.f32.f16.f16.f32 "
        "{%0,%1,%2,%3}, {%4,%5,%6,%7}, {%8,%9}, {%0,%1,%2,%3};"
        : "+f"(c[0]), "+f"(c[1]), "+f"(c[2]), "+f"(c[3])
        : "r"(a[0]), "r"(a[1]), "r"(a[2]), "r"(a[3]), "r"(b[0]), "r"(b[1]));
}

__device__ __forceinline__ void splitf(float v, __half& h, __half& m) {
    h = __float2half_rn(v);
    m = __float2half_rn(v - __half2float(h));
}

// smem tile: [128 rows][32 fp16], 64B/row, 16B chunks XOR-swizzled
__device__ __forceinline__ uint32_t tile_addr(uint32_t base, int r, int ck) {
    return base + r * 64 + (((uint32_t)(ck ^ ((r >> 1) & 3))) << 4);
}

// ===================== fp16-split tensor-core GEMM ==========================
// C[M,N] = epi( A[M,Kp] @ B[NB,Kp]^T )
// BS=2: 3 MMAs (ah*bh + ah*bm + am*bh)   BS=1: 2 MMAs (ah*b + am*b)
// EPI 0: leaky(acc+bias) -> half hi/mid
// EPI 1: acc+bias        -> fp32 + half hi/mid
// EPI 2: VQ: per-row argmin of -2*acc+embsq[n] -> block candidates (no C)
// EPI 3: acc+bias        -> fp32 (ragged N guard)
// 3 smem stages, 2 CTAs/SM.
template <int EPI, int BS>
__global__ __launch_bounds__(256, 2) void tc_gemm(
    const __half* __restrict__ Ah, const __half* __restrict__ Am,
    const __half* __restrict__ Bh, const __half* __restrict__ Bm,
    const float* __restrict__ bias, float* __restrict__ Cf,
    __half* __restrict__ Ch, __half* __restrict__ Cm,
    int N, int Kp)
{
    constexpr int STAGE_B = (BS == 2) ? 32768 : 24576;
    extern __shared__ char smem[];
    const uint32_t sb = smem_u32(smem);
    const int tid = threadIdx.x;
    const int wid = tid >> 5, lane = tid & 31;
    const int g = lane >> 2, tg = lane & 3;
    const int wm = (wid >> 2) * 64;
    const int wn = (wid & 3) * 32;
    const int m0 = blockIdx.y * 128, n0 = blockIdx.x * 128;
    const int nch = Kp >> 5;

    float acc[4][4][4];
#pragma unroll
    for (int i = 0; i < 4; i++)
#pragma unroll
        for (int j = 0; j < 4; j++)
#pragma unroll
            for (int k = 0; k < 4; k++) acc[i][j][k] = 0.f;

    auto load_stage = [&](int buf, int ch) {
        const int k0 = ch * 32;
#pragma unroll
        for (int i = 0; i < 2; i++) {
            const int id = i * 256 + tid;
            const int r = id >> 2, ck = id & 3;
            const uint32_t dst = tile_addr(sb + buf * STAGE_B, r, ck);
            const size_t ao = (size_t)(m0 + r) * Kp + k0 + ck * 8;
            const size_t bo = (size_t)(n0 + r) * Kp + k0 + ck * 8;
            CP16(dst,         Ah + ao);
            CP16(dst + 8192,  Am + ao);
            CP16(dst + 16384, Bh + bo);
            if (BS == 2) CP16(dst + 24576, Bm + bo);
        }
    };

    auto compute = [&](int buf) {
        const uint32_t ba = sb + buf * STAGE_B;
        const int rA = wm + (lane & 15), cA = lane >> 4;
        const int rB = wn + (lane & 7) + ((lane >> 4) << 3), cB = (lane >> 3) & 1;
        uint32_t aA[2], aB[2];
        aA[0] = tile_addr(ba, rA, cA);
        aA[1] = tile_addr(ba, rA, cA + 2);
        aB[0] = tile_addr(ba + 16384, rB, cB);
        aB[1] = tile_addr(ba + 16384, rB, cB + 2);
#pragma unroll
        for (int ks = 0; ks < 2; ks++) {
            uint32_t ah[4][4], am[4][4], bh[4][2], bm[4][2];
#pragma unroll
            for (int mt = 0; mt < 4; mt++) {
                LDSM4(ah[mt][0], ah[mt][1], ah[mt][2], ah[mt][3], aA[ks] + mt * 1024);
                LDSM4(am[mt][0], am[mt][1], am[mt][2], am[mt][3], aA[ks] + 8192 + mt * 1024);
            }
#pragma unroll
            for (int p = 0; p < 2; p++) {
                LDSM4(bh[2*p][0], bh[2*p][1], bh[2*p+1][0], bh[2*p+1][1], aB[ks] + p * 1024);
                if (BS == 2)
                    LDSM4(bm[2*p][0], bm[2*p][1], bm[2*p+1][0], bm[2*p+1][1],
                          aB[ks] + 8192 + p * 1024);
            }
#pragma unroll
            for (int mt = 0; mt < 4; mt++)
#pragma unroll
                for (int nt = 0; nt < 4; nt++) {
                    mma16816(acc[mt][nt], ah[mt], bh[nt]);
                    if (BS == 2) {
                        mma16816(acc[mt][nt], ah[mt], bm[nt]);
                        mma16816(acc[mt][nt], am[mt], bh[nt]);
                    } else {
                        mma16816(acc[mt][nt], am[mt], bh[nt]);
                    }
                }
        }
    };

    // ---- prologue: 2 stages in flight (3 buffers) ----
    load_stage(0, 0);
    CP_COMMIT();
    if (nch > 1) load_stage(1, 1);
    CP_COMMIT();

    // ---- main loop: wait oldest, sync, prefetch c+2 into freed buffer ----
    int buf = 0, nbuf = 2;           // buf = c % 3, nbuf = (c+2) % 3
    for (int c = 0; c < nch; c++) {
        CP_WAIT1();
        __syncthreads();
        const int nxt = c + 2;
        if (nxt < nch) load_stage(nbuf, nxt);
        CP_COMMIT();
        compute(buf);
        buf = (buf == 2) ? 0 : buf + 1;
        nbuf = (nbuf == 2) ? 0 : nbuf + 1;
    }

    if (EPI == 2) {
        // ---- fused per-row argmin over this 128-col block ----
        __syncthreads();
        float* sval = reinterpret_cast<float*>(smem);
        int*   sidx = reinterpret_cast<int*>(smem + 2048);
#pragma unroll
        for (int mt = 0; mt < 4; mt++)
#pragma unroll
            for (int hh = 0; hh < 2; hh++) {
                float bv = 3.4e38f; int bi = 0x7FFFFFFF;
#pragma unroll
                for (int nt = 0; nt < 4; nt++)
#pragma unroll
                    for (int j = 0; j < 2; j++) {
                        const int gn = n0 + wn + nt * 8 + tg * 2 + j;
                        float s = -2.f * acc[mt][nt][hh * 2 + j] + bias[gn];
                        if (s < bv || (s == bv && gn < bi)) { bv = s; bi = gn; }
                    }
#pragma unroll
                for (int o = 1; o < 4; o <<= 1) {
                    float ov = __shfl_xor_sync(0xFFFFFFFF, bv, o);
                    int   oi = __shfl_xor_sync(0xFFFFFFFF, bi, o);
                    if (ov < bv || (ov == bv && oi < bi)) { bv = ov; bi = oi; }
                }
                const int lr = wm + mt * 16 + hh * 8 + g;
                if (tg == 0) { sval[lr * 4 + (wid & 3)] = bv; sidx[lr * 4 + (wid & 3)] = bi; }
            }
        __syncthreads();
        if (tid < 128) {
            float bv = sval[tid * 4]; int bi = sidx[tid * 4];
#pragma unroll
            for (int w = 1; w < 4; w++) {
                float ov = sval[tid * 4 + w]; int oi = sidx[tid * 4 + w];
                if (ov < bv || (ov == bv && oi < bi)) { bv = ov; bi = oi; }
            }
            g_cval[(size_t)(m0 + tid) * 8 + blockIdx.x] = bv;
            g_cidx[(size_t)(m0 + tid) * 8 + blockIdx.x] = bi;
        }
        return;
    }

    // ---- standard epilogues ----
#pragma unroll
    for (int mt = 0; mt < 4; mt++)
#pragma unroll
        for (int nt = 0; nt < 4; nt++) {
            const int gn = n0 + wn + nt * 8 + tg * 2;
#pragma unroll
            for (int hh = 0; hh < 2; hh++) {
                const int gm = m0 + wm + mt * 16 + g + hh * 8;
                float v0 = acc[mt][nt][hh * 2 + 0];
                float v1 = acc[mt][nt][hh * 2 + 1];
                if (EPI == 3) {
                    if (gn < N) {
                        v0 += bias[gn]; v1 += bias[gn + 1];
                        *reinterpret_cast<float2*>(Cf + (size_t)gm * N + gn) = make_float2(v0, v1);
                    }
                } else {
                    v0 += bias[gn]; v1 += bias[gn + 1];
                    if (EPI == 0) {
                        v0 = (v0 >= 0.f) ? v0 : ALPHA * v0;
                        v1 = (v1 >= 0.f) ? v1 : ALPHA * v1;
                    }
                    __half h0, m0h, h1, m1h;
                    splitf(v0, h0, m0h);
                    splitf(v1, h1, m1h);
                    __half2 hp; hp.x = h0; hp.y = h1;
                    __half2 mp; mp.x = m0h; mp.y = m1h;
                    *reinterpret_cast<__half2*>(Ch + (size_t)gm * N + gn) = hp;
                    *reinterpret_cast<__half2*>(Cm + (size_t)gm * N + gn) = mp;
                    if (EPI == 1)
                        *reinterpret_cast<float2*>(Cf + (size_t)gm * N + gn) = make_float2(v0, v1);
                }
            }
        }
}

// ------------- x -> fp16 hi/mid with K padding ------------------------------
__global__ __launch_bounds__(256) void conv_x(const float* __restrict__ x)
{
    int i = blockIdx.x * 256 + threadIdx.x;
    if (i >= BATCH * KP1) return;
    int row = i / KP1, col = i - row * KP1;
    float v = (col < IN_DIM) ? x[(size_t)row * IN_DIM + col] : 0.f;
    __half h, m;
    splitf(v, h, m);
    g_xh[i] = h; g_xm[i] = m;
}

// ------------- weight transpose + split + pad: in[K][N] -> out[Nr][Kp] ------
// grid: (Nr/32, Kp/32)
__global__ __launch_bounds__(256) void conv_wt(
    const float* __restrict__ in, __half* __restrict__ oh,
    __half* __restrict__ om, int K, int N, int Kp, int Nr)
{
    __shared__ float t[32][33];
    const int kb = blockIdx.y * 32, nb = blockIdx.x * 32;
    const int x = threadIdx.x & 31, y4 = (threadIdx.x >> 5) * 4;
#pragma unroll
    for (int i = 0; i < 4; i++) {
        int k = kb + y4 + i, n = nb + x;
        t[y4 + i][x] = (k < K && n < N) ? in[(size_t)k * N + n] : 0.f;
    }
    __syncthreads();
#pragma unroll
    for (int i = 0; i < 4; i++) {
        int n = nb + y4 + i, k = kb + x;
        if (n < Nr && k < Kp) {
            __half h, m;
            splitf(t[x][y4 + i], h, m);
            oh[(size_t)n * Kp + k] = h;
            om[(size_t)n * Kp + k] = m;
        }
    }
}

// ------------- codebook prep: transpose + split + norms + zero loss ---------
__global__ __launch_bounds__(256) void vq_pre_kernel(const float* __restrict__ emb)
{
    const int j = blockIdx.x;
    const int tid = threadIdx.x;
    __shared__ float red[256];
    float s = 0.f;
    for (int d = tid; d < LATENT; d += 256) {
        float v = emb[(size_t)d * NUM_EMB + j];
        g_embT[(size_t)j * LATENT + d] = v;
        __half h, m;
        splitf(v, h, m);
        g_ebh[(size_t)j * LATENT + d] = h;
        g_ebm[(size_t)j * LATENT + d] = m;
        s += v * v;
    }
    red[tid] = s;
    __syncthreads();
    for (int o = 128; o > 0; o >>= 1) {
        if (tid < o) red[tid] += red[tid + o];
        __syncthreads();
    }
    if (tid == 0) g_embsq[j] = red[0];
    if (blockIdx.x == 0 && tid == 0) g_loss = 0.f;
}

// ------------- final argmin over 8 block candidates + gather + loss ---------
__global__ __launch_bounds__(256) void vq_select2()
{
    const int row = blockIdx.x * 8 + (threadIdx.x >> 5);
    const int lane = threadIdx.x & 31;
    float bv = 3.4e38f; int bi = 0x7FFFFFFF;
    if (lane < 8) { bv = g_cval[(size_t)row * 8 + lane]; bi = g_cidx[(size_t)row * 8 + lane]; }
#pragma unroll
    for (int o = 1; o < 8; o <<= 1) {
        float ov = __shfl_xor_sync(0xFFFFFFFF, bv, o);
        int   oi = __shfl_xor_sync(0xFFFFFFFF, bi, o);
        if (ov < bv || (ov == bv && oi < bi)) { bv = ov; bi = oi; }
    }
    const int j = __shfl_sync(0xFFFFFFFF, bi, 0);

    const float* e  = g_embT + (size_t)j * LATENT;
    const float* zr = g_z    + (size_t)row * LATENT;
    float ls = 0.f;
#pragma unroll
    for (int d = lane; d < LATENT; d += 32) {
        float q = e[d];
        __half h, m;
        splitf(q, h, m);
        g_qh[(size_t)row * LATENT + d] = h;
        g_qm[(size_t)row * LATENT + d] = m;
        float df = q - zr[d];
        ls += df * df;
    }
#pragma unroll
    for (int o = 16; o > 0; o >>= 1)
        ls += __shfl_xor_sync(0xFFFFFFFF, ls, o);
    if (lane == 0) atomicAdd(&g_loss, ls);
}

__global__ void finalize_kernel(float* __restrict__ out, long long pos)
{
    out[pos] = 1.25f * g_loss / (float)((long long)BATCH * LATENT);
}

// ---------------------------------------------------------------------------
extern "C" void kernel_launch(void* const* d_in, const int* in_sizes, int n_in,
                              void* d_out, int out_size)
{
    const float* x   = (const float*)d_in[0];
    const float* W1  = (const float*)d_in[1];
    const float* b1  = (const float*)d_in[2];
    const float* W2  = (const float*)d_in[3];
    const float* b2  = (const float*)d_in[4];
    const float* emb = (const float*)d_in[5];
    const float* W3  = (const float*)d_in[6];
    const float* b3  = (const float*)d_in[7];
    const float* W4  = (const float*)d_in[8];
    const float* b4  = (const float*)d_in[9];
    float* out = (float*)d_out;

    __half *xh, *xm, *hh, *hm, *zh, *zm, *qh, *qm, *ebh, *ebm;
    __half *w1h, *w1m, *w2h, *w2m, *w3h, *w3m, *w4h, *w4m;
    float *z, *embsq;
    cudaGetSymbolAddress((void**)&xh,  g_xh);  cudaGetSymbolAddress((void**)&xm,  g_xm);
    cudaGetSymbolAddress((void**)&hh,  g_hh);  cudaGetSymbolAddress((void**)&hm,  g_hm);
    cudaGetSymbolAddress((void**)&zh,  g_zh);  cudaGetSymbolAddress((void**)&zm,  g_zm);
    cudaGetSymbolAddress((void**)&qh,  g_qh);  cudaGetSymbolAddress((void**)&qm,  g_qm);
    cudaGetSymbolAddress((void**)&ebh, g_ebh); cudaGetSymbolAddress((void**)&ebm, g_ebm);
    cudaGetSymbolAddress((void**)&w1h, g_w1h); cudaGetSymbolAddress((void**)&w1m, g_w1m);
    cudaGetSymbolAddress((void**)&w2h, g_w2h); cudaGetSymbolAddress((void**)&w2m, g_w2m);
    cudaGetSymbolAddress((void**)&w3h, g_w3h); cudaGetSymbolAddress((void**)&w3m, g_w3m);
    cudaGetSymbolAddress((void**)&w4h, g_w4h); cudaGetSymbolAddress((void**)&w4m, g_w4m);
    cudaGetSymbolAddress((void**)&z,   g_z);
    cudaGetSymbolAddress((void**)&embsq, g_embsq);

    const int SM2 = 3 * 32768;   // BS=2: 96KB -> 2 CTAs/SM
    const int SM1 = 3 * 24576;   // BS=1: 72KB -> 2 CTAs/SM
    cudaFuncSetAttribute((const void*)tc_gemm<0,2>, cudaFuncAttributeMaxDynamicSharedMemorySize, SM2);
    cudaFuncSetAttribute((const void*)tc_gemm<1,2>, cudaFuncAttributeMaxDynamicSharedMemorySize, SM2);
    cudaFuncSetAttribute((const void*)tc_gemm<2,2>, cudaFuncAttributeMaxDynamicSharedMemorySize, SM2);
    cudaFuncSetAttribute((const void*)tc_gemm<0,1>, cudaFuncAttributeMaxDynamicSharedMemorySize, SM1);
    cudaFuncSetAttribute((const void*)tc_gemm<3,1>, cudaFuncAttributeMaxDynamicSharedMemorySize, SM1);

    const dim3 blk(256);

    // 0. conversions / prep
    conv_x<<<(BATCH * KP1 + 255) / 256, blk>>>(x);
    conv_wt<<<dim3(H_ENC / 32,  KP1 / 32),    blk>>>(W1, w1h, w1m, IN_DIM, H_ENC,  KP1,    H_ENC);
    conv_wt<<<dim3(LATENT / 32, H_ENC / 32),  blk>>>(W2, w2h, w2m, H_ENC,  LATENT, H_ENC,  LATENT);
    conv_wt<<<dim3(H_DEC / 32,  LATENT / 32), blk>>>(W3, w3h, w3m, LATENT, H_DEC,  LATENT, H_DEC);
    conv_wt<<<dim3(NB4 / 32,    H_DEC / 32),  blk>>>(W4, w4h, w4m, H_DEC,  OUT_DIM, H_DEC, NB4);
    vq_pre_kernel<<<NUM_EMB, blk>>>(emb);

    // 1. h = leaky(x @ W1 + b1)  -> fp16 pair   (3-MMA path)
    tc_gemm<0,2><<<dim3(H_ENC / 128, BATCH / 128), blk, SM2>>>(
        xh, xm, w1h, w1m, b1, nullptr, hh, hm, H_ENC, KP1);
    // 2. z = h @ W2 + b2  -> fp32 + fp16 pair   (3-MMA path)
    tc_gemm<1,2><<<dim3(LATENT / 128, BATCH / 128), blk, SM2>>>(
        hh, hm, w2h, w2m, b2, z, zh, zm, LATENT, H_ENC);
    // 3. VQ scores + fused per-block argmin     (3-MMA path)
    tc_gemm<2,2><<<dim3(NUM_EMB / 128, BATCH / 128), blk, SM2>>>(
        zh, zm, ebh, ebm, embsq, nullptr, nullptr, nullptr, NUM_EMB, LATENT);
    // 4. final argmin + gather + loss
    vq_select2<<<BATCH / 8, blk>>>();
    // 5. h2 = leaky(q @ W3 + b3)  -> fp16 pair  (2-MMA path, B single fp16)
    tc_gemm<0,1><<<dim3(H_DEC / 128, BATCH / 128), blk, SM1>>>(
        qh, qm, w3h, nullptr, b3, nullptr, hh, hm, H_DEC, LATENT);
    // 6. recon = h2 @ W4 + b4 -> fp32 out       (2-MMA path)
    tc_gemm<3,1><<<dim3((OUT_DIM + 127) / 128, BATCH / 128), blk, SM1>>>(
        hh, hm, w4h, nullptr, b4, out, nullptr, nullptr, OUT_DIM, H_DEC);
    // 7. scalar loss
    finalize_kernel<<<1, 1>>>(out, (long long)out_size - 1);
}

// round 12
// speedup vs baseline: 5.0069x; 1.3975x over previous
#include <cuda_runtime.h>
#include <cuda_fp16.h>
#include <cstdint>

#define BATCH   16384
#define IN_DIM  700
#define H_ENC   2048
#define LATENT  512
#define H_DEC   2048
#define OUT_DIM 700
#define NUM_EMB 1024
#define ALPHA   0.2f

#define KP1 704   // IN_DIM padded to multiple of 32
#define NB4 768   // OUT_DIM padded to multiple of 128

// ---------------- scratch (static __device__, no runtime allocation) --------
__device__ __align__(128) __half g_xh[BATCH * KP1];
__device__ __align__(128) __half g_xm[BATCH * KP1];
__device__ __align__(128) __half g_hh[BATCH * H_ENC];
__device__ __align__(128) __half g_hm[BATCH * H_ENC];
__device__ __align__(128) float  g_z[BATCH * LATENT];
__device__ __align__(128) __half g_zh[BATCH * LATENT];
__device__ __align__(128) __half g_zm[BATCH * LATENT];
__device__ __align__(128) float  g_embT[NUM_EMB * LATENT];
__device__ __align__(128) __half g_ebh[NUM_EMB * LATENT];
__device__ __align__(128) __half g_ebm[NUM_EMB * LATENT];
__device__ float g_embsq[NUM_EMB];
__device__ float g_loss;
__device__ __align__(128) float g_cval[BATCH * 8];
__device__ __align__(128) int   g_cidx[BATCH * 8];
// decoder tables (forward value of q_st is exactly the codebook entry!)
__device__ __align__(128) __half g_hdh[NUM_EMB * H_DEC];   // leaky(emb@W3+b3) hi
__device__ __align__(128) __half g_hdm[NUM_EMB * H_DEC];   // mid
__device__ __align__(128) float  g_rt[NUM_EMB * OUT_DIM];  // full recon table
// weights
__device__ __align__(128) __half g_w1h[H_ENC * KP1];
__device__ __align__(128) __half g_w1m[H_ENC * KP1];
__device__ __align__(128) __half g_w2h[LATENT * H_ENC];
__device__ __align__(128) __half g_w2m[LATENT * H_ENC];
__device__ __align__(128) __half g_w3h[H_DEC * LATENT];
__device__ __align__(128) __half g_w3m[H_DEC * LATENT];
__device__ __align__(128) __half g_w4h[NB4 * H_DEC];
__device__ __align__(128) __half g_w4m[NB4 * H_DEC];

// ======================= helpers ===========================================
__device__ __forceinline__ uint32_t smem_u32(const void* p) {
    uint32_t a;
    asm("{ .reg .u64 t; cvta.to.shared.u64 t, %1; cvt.u32.u64 %0, t; }"
        : "=r"(a) : "l"(p));
    return a;
}
#define CP16(dst, src) \
    asm volatile("cp.async.cg.shared.global [%0], [%1], 16;" :: "r"(dst), "l"(src))
#define CP_COMMIT() asm volatile("cp.async.commit_group;")
#define CP_WAIT1()  asm volatile("cp.async.wait_group 1;")

#define LDSM4(r0, r1, r2, r3, a) \
    asm volatile("ldmatrix.sync.aligned.m8n8.x4.shared.b16 {%0,%1,%2,%3}, [%4];" \
        : "=r"(r0), "=r"(r1), "=r"(r2), "=r"(r3) : "r"(a))

__device__ __forceinline__ void mma16816(float* c, const uint32_t* a, const uint32_t* b) {
    asm volatile(
        "mma.sync.aligned.m16n8k16.row.col.f32.f16.f16.f32 "
        "{%0,%1,%2,%3}, {%4,%5,%6,%7}, {%8,%9}, {%0,%1,%2,%3};"
        : "+f"(c[0]), "+f"(c[1]), "+f"(c[2]), "+f"(c[3])
        : "r"(a[0]), "r"(a[1]), "r"(a[2]), "r"(a[3]), "r"(b[0]), "r"(b[1]));
}

__device__ __forceinline__ void splitf(float v, __half& h, __half& m) {
    h = __float2half_rn(v);
    m = __float2half_rn(v - __half2float(h));
}

// smem tile: [128 rows][32 fp16], 64B/row, 16B chunks XOR-swizzled
__device__ __forceinline__ uint32_t tile_addr(uint32_t base, int r, int ck) {
    return base + r * 64 + (((uint32_t)(ck ^ ((r >> 1) & 3))) << 4);
}

// ===================== fp16-split tensor-core GEMM ==========================
// C[M,N] = epi( A[M,Kp] @ B[NB,Kp]^T ), 3-MMA split everywhere (BS=2)
// EPI 0: leaky(acc+bias) -> half hi/mid
// EPI 1: acc+bias        -> fp32 + half hi/mid
// EPI 2: VQ: per-row argmin of -2*acc+embsq[n] -> block candidates (no C)
// EPI 3: acc+bias        -> fp32 (ragged N guard)
// 3 smem stages, 2 CTAs/SM.
template <int EPI>
__global__ __launch_bounds__(256, 2) void tc_gemm(
    const __half* __restrict__ Ah, const __half* __restrict__ Am,
    const __half* __restrict__ Bh, const __half* __restrict__ Bm,
    const float* __restrict__ bias, float* __restrict__ Cf,
    __half* __restrict__ Ch, __half* __restrict__ Cm,
    int N, int Kp)
{
    constexpr int STAGE_B = 32768;
    extern __shared__ char smem[];
    const uint32_t sb = smem_u32(smem);
    const int tid = threadIdx.x;
    const int wid = tid >> 5, lane = tid & 31;
    const int g = lane >> 2, tg = lane & 3;
    const int wm = (wid >> 2) * 64;
    const int wn = (wid & 3) * 32;
    const int m0 = blockIdx.y * 128, n0 = blockIdx.x * 128;
    const int nch = Kp >> 5;

    float acc[4][4][4];
#pragma unroll
    for (int i = 0; i < 4; i++)
#pragma unroll
        for (int j = 0; j < 4; j++)
#pragma unroll
            for (int k = 0; k < 4; k++) acc[i][j][k] = 0.f;

    auto load_stage = [&](int buf, int ch) {
        const int k0 = ch * 32;
#pragma unroll
        for (int i = 0; i < 2; i++) {
            const int id = i * 256 + tid;
            const int r = id >> 2, ck = id & 3;
            const uint32_t dst = tile_addr(sb + buf * STAGE_B, r, ck);
            const size_t ao = (size_t)(m0 + r) * Kp + k0 + ck * 8;
            const size_t bo = (size_t)(n0 + r) * Kp + k0 + ck * 8;
            CP16(dst,         Ah + ao);
            CP16(dst + 8192,  Am + ao);
            CP16(dst + 16384, Bh + bo);
            CP16(dst + 24576, Bm + bo);
        }
    };

    auto compute = [&](int buf) {
        const uint32_t ba = sb + buf * STAGE_B;
        const int rA = wm + (lane & 15), cA = lane >> 4;
        const int rB = wn + (lane & 7) + ((lane >> 4) << 3), cB = (lane >> 3) & 1;
        uint32_t aA[2], aB[2];
        aA[0] = tile_addr(ba, rA, cA);
        aA[1] = tile_addr(ba, rA, cA + 2);
        aB[0] = tile_addr(ba + 16384, rB, cB);
        aB[1] = tile_addr(ba + 16384, rB, cB + 2);
#pragma unroll
        for (int ks = 0; ks < 2; ks++) {
            uint32_t ah[4][4], am[4][4], bh[4][2], bm[4][2];
#pragma unroll
            for (int mt = 0; mt < 4; mt++) {
                LDSM4(ah[mt][0], ah[mt][1], ah[mt][2], ah[mt][3], aA[ks] + mt * 1024);
                LDSM4(am[mt][0], am[mt][1], am[mt][2], am[mt][3], aA[ks] + 8192 + mt * 1024);
            }
#pragma unroll
            for (int p = 0; p < 2; p++) {
                LDSM4(bh[2*p][0], bh[2*p][1], bh[2*p+1][0], bh[2*p+1][1], aB[ks] + p * 1024);
                LDSM4(bm[2*p][0], bm[2*p][1], bm[2*p+1][0], bm[2*p+1][1],
                      aB[ks] + 8192 + p * 1024);
            }
#pragma unroll
            for (int mt = 0; mt < 4; mt++)
#pragma unroll
                for (int nt = 0; nt < 4; nt++) {
                    mma16816(acc[mt][nt], ah[mt], bh[nt]);
                    mma16816(acc[mt][nt], ah[mt], bm[nt]);
                    mma16816(acc[mt][nt], am[mt], bh[nt]);
                }
        }
    };

    // ---- prologue: 2 stages in flight (3 buffers) ----
    load_stage(0, 0);
    CP_COMMIT();
    if (nch > 1) load_stage(1, 1);
    CP_COMMIT();

    int buf = 0, nbuf = 2;
    for (int c = 0; c < nch; c++) {
        CP_WAIT1();
        __syncthreads();
        const int nxt = c + 2;
        if (nxt < nch) load_stage(nbuf, nxt);
        CP_COMMIT();
        compute(buf);
        buf = (buf == 2) ? 0 : buf + 1;
        nbuf = (nbuf == 2) ? 0 : nbuf + 1;
    }

    if (EPI == 2) {
        __syncthreads();
        float* sval = reinterpret_cast<float*>(smem);
        int*   sidx = reinterpret_cast<int*>(smem + 2048);
#pragma unroll
        for (int mt = 0; mt < 4; mt++)
#pragma unroll
            for (int hh = 0; hh < 2; hh++) {
                float bv = 3.4e38f; int bi = 0x7FFFFFFF;
#pragma unroll
                for (int nt = 0; nt < 4; nt++)
#pragma unroll
                    for (int j = 0; j < 2; j++) {
                        const int gn = n0 + wn + nt * 8 + tg * 2 + j;
                        float s = -2.f * acc[mt][nt][hh * 2 + j] + bias[gn];
                        if (s < bv || (s == bv && gn < bi)) { bv = s; bi = gn; }
                    }
#pragma unroll
                for (int o = 1; o < 4; o <<= 1) {
                    float ov = __shfl_xor_sync(0xFFFFFFFF, bv, o);
                    int   oi = __shfl_xor_sync(0xFFFFFFFF, bi, o);
                    if (ov < bv || (ov == bv && oi < bi)) { bv = ov; bi = oi; }
                }
                const int lr = wm + mt * 16 + hh * 8 + g;
                if (tg == 0) { sval[lr * 4 + (wid & 3)] = bv; sidx[lr * 4 + (wid & 3)] = bi; }
            }
        __syncthreads();
        if (tid < 128) {
            float bv = sval[tid * 4]; int bi = sidx[tid * 4];
#pragma unroll
            for (int w = 1; w < 4; w++) {
                float ov = sval[tid * 4 + w]; int oi = sidx[tid * 4 + w];
                if (ov < bv || (ov == bv && oi < bi)) { bv = ov; bi = oi; }
            }
            g_cval[(size_t)(m0 + tid) * 8 + blockIdx.x] = bv;
            g_cidx[(size_t)(m0 + tid) * 8 + blockIdx.x] = bi;
        }
        return;
    }

#pragma unroll
    for (int mt = 0; mt < 4; mt++)
#pragma unroll
        for (int nt = 0; nt < 4; nt++) {
            const int gn = n0 + wn + nt * 8 + tg * 2;
#pragma unroll
            for (int hh = 0; hh < 2; hh++) {
                const int gm = m0 + wm + mt * 16 + g + hh * 8;
                float v0 = acc[mt][nt][hh * 2 + 0];
                float v1 = acc[mt][nt][hh * 2 + 1];
                if (EPI == 3) {
                    if (gn < N) {
                        v0 += bias[gn]; v1 += bias[gn + 1];
                        *reinterpret_cast<float2*>(Cf + (size_t)gm * N + gn) = make_float2(v0, v1);
                    }
                } else {
                    v0 += bias[gn]; v1 += bias[gn + 1];
                    if (EPI == 0) {
                        v0 = (v0 >= 0.f) ? v0 : ALPHA * v0;
                        v1 = (v1 >= 0.f) ? v1 : ALPHA * v1;
                    }
                    __half h0, m0h, h1, m1h;
                    splitf(v0, h0, m0h);
                    splitf(v1, h1, m1h);
                    __half2 hp; hp.x = h0; hp.y = h1;
                    __half2 mp; mp.x = m0h; mp.y = m1h;
                    *reinterpret_cast<__half2*>(Ch + (size_t)gm * N + gn) = hp;
                    *reinterpret_cast<__half2*>(Cm + (size_t)gm * N + gn) = mp;
                    if (EPI == 1)
                        *reinterpret_cast<float2*>(Cf + (size_t)gm * N + gn) = make_float2(v0, v1);
                }
            }
        }
}

// ------------- x -> fp16 hi/mid with K padding ------------------------------
__global__ __launch_bounds__(256) void conv_x(const float* __restrict__ x)
{
    int i = blockIdx.x * 256 + threadIdx.x;
    if (i >= BATCH * KP1) return;
    int row = i / KP1, col = i - row * KP1;
    float v = (col < IN_DIM) ? x[(size_t)row * IN_DIM + col] : 0.f;
    __half h, m;
    splitf(v, h, m);
    g_xh[i] = h; g_xm[i] = m;
}

// ------------- weight transpose + split + pad: in[K][N] -> out[Nr][Kp] ------
// grid: (Nr/32, Kp/32)
__global__ __launch_bounds__(256) void conv_wt(
    const float* __restrict__ in, __half* __restrict__ oh,
    __half* __restrict__ om, int K, int N, int Kp, int Nr)
{
    __shared__ float t[32][33];
    const int kb = blockIdx.y * 32, nb = blockIdx.x * 32;
    const int x = threadIdx.x & 31, y4 = (threadIdx.x >> 5) * 4;
#pragma unroll
    for (int i = 0; i < 4; i++) {
        int k = kb + y4 + i, n = nb + x;
        t[y4 + i][x] = (k < K && n < N) ? in[(size_t)k * N + n] : 0.f;
    }
    __syncthreads();
#pragma unroll
    for (int i = 0; i < 4; i++) {
        int n = nb + y4 + i, k = kb + x;
        if (n < Nr && k < Kp) {
            __half h, m;
            splitf(t[x][y4 + i], h, m);
            oh[(size_t)n * Kp + k] = h;
            om[(size_t)n * Kp + k] = m;
        }
    }
}

// ------------- codebook prep: transpose + split + norms + zero loss ---------
__global__ __launch_bounds__(256) void vq_pre_kernel(const float* __restrict__ emb)
{
    const int j = blockIdx.x;
    const int tid = threadIdx.x;
    __shared__ float red[256];
    float s = 0.f;
    for (int d = tid; d < LATENT; d += 256) {
        float v = emb[(size_t)d * NUM_EMB + j];
        g_embT[(size_t)j * LATENT + d] = v;
        __half h, m;
        splitf(v, h, m);
        g_ebh[(size_t)j * LATENT + d] = h;
        g_ebm[(size_t)j * LATENT + d] = m;
        s += v * v;
    }
    red[tid] = s;
    __syncthreads();
    for (int o = 128; o > 0; o >>= 1) {
        if (tid < o) red[tid] += red[tid + o];
        __syncthreads();
    }
    if (tid == 0) g_embsq[j] = red[0];
    if (blockIdx.x == 0 && tid == 0) g_loss = 0.f;
}

// ------- final argmin over 8 candidates + loss + recon-table gather ---------
__global__ __launch_bounds__(256) void vq_select2(float* __restrict__ out)
{
    const int row = blockIdx.x * 8 + (threadIdx.x >> 5);
    const int lane = threadIdx.x & 31;
    float bv = 3.4e38f; int bi = 0x7FFFFFFF;
    if (lane < 8) { bv = g_cval[(size_t)row * 8 + lane]; bi = g_cidx[(size_t)row * 8 + lane]; }
#pragma unroll
    for (int o = 1; o < 8; o <<= 1) {
        float ov = __shfl_xor_sync(0xFFFFFFFF, bv, o);
        int   oi = __shfl_xor_sync(0xFFFFFFFF, bi, o);
        if (ov < bv || (ov == bv && oi < bi)) { bv = ov; bi = oi; }
    }
    const int j = __shfl_sync(0xFFFFFFFF, bi, 0);

    // commitment/codebook loss partial: sum (emb_j - z)^2
    const float* e  = g_embT + (size_t)j * LATENT;
    const float* zr = g_z    + (size_t)row * LATENT;
    float ls = 0.f;
#pragma unroll 4
    for (int d = lane; d < LATENT; d += 32) {
        float df = e[d] - zr[d];
        ls += df * df;
    }
#pragma unroll
    for (int o = 16; o > 0; o >>= 1)
        ls += __shfl_xor_sync(0xFFFFFFFF, ls, o);
    if (lane == 0) atomicAdd(&g_loss, ls);

    // recon = decoder table row (q_st forward value == codebook entry)
    const float2* rrow = reinterpret_cast<const float2*>(g_rt + (size_t)j * OUT_DIM);
    float2* orow = reinterpret_cast<float2*>(out + (size_t)row * OUT_DIM);
#pragma unroll 4
    for (int d = lane; d < OUT_DIM / 2; d += 32)
        orow[d] = rrow[d];
}

__global__ void finalize_kernel(float* __restrict__ out, long long pos)
{
    out[pos] = 1.25f * g_loss / (float)((long long)BATCH * LATENT);
}

// ---------------------------------------------------------------------------
extern "C" void kernel_launch(void* const* d_in, const int* in_sizes, int n_in,
                              void* d_out, int out_size)
{
    const float* x   = (const float*)d_in[0];
    const float* W1  = (const float*)d_in[1];
    const float* b1  = (const float*)d_in[2];
    const float* W2  = (const float*)d_in[3];
    const float* b2  = (const float*)d_in[4];
    const float* emb = (const float*)d_in[5];
    const float* W3  = (const float*)d_in[6];
    const float* b3  = (const float*)d_in[7];
    const float* W4  = (const float*)d_in[8];
    const float* b4  = (const float*)d_in[9];
    float* out = (float*)d_out;

    __half *xh, *xm, *hh, *hm, *zh, *zm, *ebh, *ebm, *hdh, *hdm;
    __half *w1h, *w1m, *w2h, *w2m, *w3h, *w3m, *w4h, *w4m;
    float *z, *embsq, *rt;
    cudaGetSymbolAddress((void**)&xh,  g_xh);  cudaGetSymbolAddress((void**)&xm,  g_xm);
    cudaGetSymbolAddress((void**)&hh,  g_hh);  cudaGetSymbolAddress((void**)&hm,  g_hm);
    cudaGetSymbolAddress((void**)&zh,  g_zh);  cudaGetSymbolAddress((void**)&zm,  g_zm);
    cudaGetSymbolAddress((void**)&ebh, g_ebh); cudaGetSymbolAddress((void**)&ebm, g_ebm);
    cudaGetSymbolAddress((void**)&hdh, g_hdh); cudaGetSymbolAddress((void**)&hdm, g_hdm);
    cudaGetSymbolAddress((void**)&w1h, g_w1h); cudaGetSymbolAddress((void**)&w1m, g_w1m);
    cudaGetSymbolAddress((void**)&w2h, g_w2h); cudaGetSymbolAddress((void**)&w2m, g_w2m);
    cudaGetSymbolAddress((void**)&w3h, g_w3h); cudaGetSymbolAddress((void**)&w3m, g_w3m);
    cudaGetSymbolAddress((void**)&w4h, g_w4h); cudaGetSymbolAddress((void**)&w4m, g_w4m);
    cudaGetSymbolAddress((void**)&z,   g_z);
    cudaGetSymbolAddress((void**)&embsq, g_embsq);
    cudaGetSymbolAddress((void**)&rt,  g_rt);

    const int SM2 = 3 * 32768;   // 96KB -> 2 CTAs/SM
    cudaFuncSetAttribute((const void*)tc_gemm<0>, cudaFuncAttributeMaxDynamicSharedMemorySize, SM2);
    cudaFuncSetAttribute((const void*)tc_gemm<1>, cudaFuncAttributeMaxDynamicSharedMemorySize, SM2);
    cudaFuncSetAttribute((const void*)tc_gemm<2>, cudaFuncAttributeMaxDynamicSharedMemorySize, SM2);
    cudaFuncSetAttribute((const void*)tc_gemm<3>, cudaFuncAttributeMaxDynamicSharedMemorySize, SM2);

    const dim3 blk(256);

    // 0. conversions / prep
    conv_x<<<(BATCH * KP1 + 255) / 256, blk>>>(x);
    conv_wt<<<dim3(H_ENC / 32,  KP1 / 32),    blk>>>(W1, w1h, w1m, IN_DIM, H_ENC,  KP1,    H_ENC);
    conv_wt<<<dim3(LATENT / 32, H_ENC / 32),  blk>>>(W2, w2h, w2m, H_ENC,  LATENT, H_ENC,  LATENT);
    conv_wt<<<dim3(H_DEC / 32,  LATENT / 32), blk>>>(W3, w3h, w3m, LATENT, H_DEC,  LATENT, H_DEC);
    conv_wt<<<dim3(NB4 / 32,    H_DEC / 32),  blk>>>(W4, w4h, w4m, H_DEC,  OUT_DIM, H_DEC, NB4);
    vq_pre_kernel<<<NUM_EMB, blk>>>(emb);

    // 0b. decoder tables over the 1024 codebook entries (tiny GEMMs, 3-MMA)
    //     hd = leaky(embT @ W3 + b3)   [1024, 2048] fp16 pair
    tc_gemm<0><<<dim3(H_DEC / 128, NUM_EMB / 128), blk, SM2>>>(
        ebh, ebm, w3h, w3m, b3, nullptr, hdh, hdm, H_DEC, LATENT);
    //     rt = hd @ W4 + b4            [1024, 700] fp32 (ragged)
    tc_gemm<3><<<dim3((OUT_DIM + 127) / 128, NUM_EMB / 128), blk, SM2>>>(
        hdh, hdm, w4h, w4m, b4, rt, nullptr, nullptr, OUT_DIM, H_DEC);

    // 1. h = leaky(x @ W1 + b1)  -> fp16 pair
    tc_gemm<0><<<dim3(H_ENC / 128, BATCH / 128), blk, SM2>>>(
        xh, xm, w1h, w1m, b1, nullptr, hh, hm, H_ENC, KP1);
    // 2. z = h @ W2 + b2  -> fp32 + fp16 pair
    tc_gemm<1><<<dim3(LATENT / 128, BATCH / 128), blk, SM2>>>(
        hh, hm, w2h, w2m, b2, z, zh, zm, LATENT, H_ENC);
    // 3. VQ scores + fused per-block argmin
    tc_gemm<2><<<dim3(NUM_EMB / 128, BATCH / 128), blk, SM2>>>(
        zh, zm, ebh, ebm, embsq, nullptr, nullptr, nullptr, NUM_EMB, LATENT);
    // 4. final argmin + loss + recon gather from table
    vq_select2<<<BATCH / 8, blk>>>(out);
    // 5. scalar loss
    finalize_kernel<<<1, 1>>>(out, (long long)out_size - 1);
}

// round 17
// speedup vs baseline: 5.6047x; 1.1194x over previous
#include <cuda_runtime.h>
#include <cuda_fp16.h>
#include <cstdint>

#define BATCH   16384
#define IN_DIM  700
#define H_ENC   2048
#define LATENT  512
#define H_DEC   2048
#define OUT_DIM 700
#define NUM_EMB 1024
#define ALPHA   0.2f

#define KP1 704   // IN_DIM padded to multiple of 32
#define NB4 768   // OUT_DIM padded to multiple of 128
#define RT_STRIDE (NUM_EMB * OUT_DIM)   // 716800

// ---------------- scratch (static __device__, no runtime allocation) --------
__device__ __align__(128) __half g_xh[BATCH * KP1];
__device__ __align__(128) __half g_xm[BATCH * KP1];
__device__ __align__(128) __half g_hh[BATCH * H_ENC];
__device__ __align__(128) __half g_hm[BATCH * H_ENC];
__device__ __align__(128) __half g_zh[BATCH * LATENT];
__device__ __align__(128) __half g_zm[BATCH * LATENT];
__device__ __align__(128) float  g_embT[NUM_EMB * LATENT];
__device__ __align__(128) __half g_ebh[NUM_EMB * LATENT];
__device__ __align__(128) __half g_ebm[NUM_EMB * LATENT];
__device__ float g_embsq[NUM_EMB];
__device__ float g_loss;
__device__ __align__(128) float g_cval[BATCH * 8];
__device__ __align__(128) int   g_cidx[BATCH * 8];
// decoder tables (forward value of q_st is exactly the codebook entry)
__device__ __align__(128) __half g_hdh[NUM_EMB * H_DEC];
__device__ __align__(128) __half g_hdm[NUM_EMB * H_DEC];
__device__ __align__(128) float  g_rtp[4 * RT_STRIDE];     // split-K partials
__device__ __align__(128) float  g_rt[RT_STRIDE];          // final recon table
// weights
__device__ __align__(128) __half g_w1h[H_ENC * KP1];
__device__ __align__(128) __half g_w1m[H_ENC * KP1];
__device__ __align__(128) __half g_w2h[LATENT * H_ENC];
__device__ __align__(128) __half g_w2m[LATENT * H_ENC];
__device__ __align__(128) __half g_w3h[H_DEC * LATENT];
__device__ __align__(128) __half g_w3m[H_DEC * LATENT];
__device__ __align__(128) __half g_w4h[NB4 * H_DEC];
__device__ __align__(128) __half g_w4m[NB4 * H_DEC];

// ======================= helpers ===========================================
__device__ __forceinline__ uint32_t smem_u32(const void* p) {
    uint32_t a;
    asm("{ .reg .u64 t; cvta.to.shared.u64 t, %1; cvt.u32.u64 %0, t; }"
        : "=r"(a) : "l"(p));
    return a;
}
#define CP16(dst, src) \
    asm volatile("cp.async.cg.shared.global [%0], [%1], 16;" :: "r"(dst), "l"(src))
#define CP_COMMIT() asm volatile("cp.async.commit_group;")
#define CP_WAIT1()  asm volatile("cp.async.wait_group 1;")

#define LDSM4(r0, r1, r2, r3, a) \
    asm volatile("ldmatrix.sync.aligned.m8n8.x4.shared.b16 {%0,%1,%2,%3}, [%4];" \
        : "=r"(r0), "=r"(r1), "=r"(r2), "=r"(r3) : "r"(a))

__device__ __forceinline__ void mma16816(float* c, const uint32_t* a, const uint32_t* b) {
    asm volatile(
        "mma.sync.aligned.m16n8k16.row.col.f32.f16.f16.f32 "
        "{%0,%1,%2,%3}, {%4,%5,%6,%7}, {%8,%9}, {%0,%1,%2,%3};"
        : "+f"(c[0]), "+f"(c[1]), "+f"(c[2]), "+f"(c[3])
        : "r"(a[0]), "r"(a[1]), "r"(a[2]), "r"(a[3]), "r"(b[0]), "r"(b[1]));
}

__device__ __forceinline__ void splitf(float v, __half& h, __half& m) {
    h = __float2half_rn(v);
    m = __float2half_rn(v - __half2float(h));
}

// smem tile: [128 rows][32 fp16], 64B/row, 16B chunks XOR-swizzled
__device__ __forceinline__ uint32_t tile_addr(uint32_t base, int r, int ck) {
    return base + r * 64 + (((uint32_t)(ck ^ ((r >> 1) & 3))) << 4);
}

// ===================== dual-region fp16-split tensor-core GEMM ==============
// One kernel; blockIdx.y < ySplit -> args a (main GEMM), else args b (aux).
// epi 0: leaky(acc+bias) -> half hi/mid pair
// epi 1: acc+bias        -> half hi/mid pair
// epi 2: VQ argmin of -2*acc+bias[n] -> per-block candidates
// epi 4: raw acc -> fp32 ragged (split-K partial, no bias)
struct GArgs {
    const __half *Ah, *Am, *Bh, *Bm;
    const float* bias;
    float* Cf;
    __half *Ch, *Cm;
    int N, Kp, ldA, ldB, xDim, epi;
};

#define STAGE_B 32768
#define SMEM_DYN (3 * STAGE_B)

__global__ __launch_bounds__(256, 2) void tc_dual(GArgs a, GArgs b, int ySplit)
{
    GArgs ga;
    int m0;
    if ((int)blockIdx.y < ySplit) {
        if ((int)blockIdx.x >= a.xDim) return;
        ga = a;
        m0 = blockIdx.y * 128;
    } else {
        if ((int)blockIdx.x >= b.xDim) return;
        ga = b;
        const int local = blockIdx.y - ySplit;
        if (ga.epi == 4) {            // split-K: 8 m-blocks x 4 k-slices
            const int slice = local >> 3, mb = local & 7;
            m0 = mb * 128;
            ga.Ah += slice * 512; ga.Am += slice * 512;
            ga.Bh += slice * 512; ga.Bm += slice * 512;
            ga.Cf += (size_t)slice * RT_STRIDE;
        } else {
            m0 = local * 128;
        }
    }

    extern __shared__ char smem[];
    const uint32_t sb = smem_u32(smem);
    const int tid = threadIdx.x;
    const int wid = tid >> 5, lane = tid & 31;
    const int gq = lane >> 2, tg = lane & 3;
    const int wm = (wid >> 2) * 64;
    const int wn = (wid & 3) * 32;
    const int n0 = blockIdx.x * 128;
    const int nch = ga.Kp >> 5;

    float acc[4][4][4];
#pragma unroll
    for (int i = 0; i < 4; i++)
#pragma unroll
        for (int j = 0; j < 4; j++)
#pragma unroll
            for (int k = 0; k < 4; k++) acc[i][j][k] = 0.f;

    auto load_stage = [&](int buf, int ch) {
        const int k0 = ch * 32;
#pragma unroll
        for (int i = 0; i < 2; i++) {
            const int id = i * 256 + tid;
            const int r = id >> 2, ck = id & 3;
            const uint32_t dst = tile_addr(sb + buf * STAGE_B, r, ck);
            const size_t ao = (size_t)(m0 + r) * ga.ldA + k0 + ck * 8;
            const size_t bo = (size_t)(n0 + r) * ga.ldB + k0 + ck * 8;
            CP16(dst,         ga.Ah + ao);
            CP16(dst + 8192,  ga.Am + ao);
            CP16(dst + 16384, ga.Bh + bo);
            CP16(dst + 24576, ga.Bm + bo);
        }
    };

    auto compute = [&](int buf) {
        const uint32_t ba = sb + buf * STAGE_B;
        const int rA = wm + (lane & 15), cA = lane >> 4;
        const int rB = wn + (lane & 7) + ((lane >> 4) << 3), cB = (lane >> 3) & 1;
        uint32_t aA[2], aB[2];
        aA[0] = tile_addr(ba, rA, cA);
        aA[1] = tile_addr(ba, rA, cA + 2);
        aB[0] = tile_addr(ba + 16384, rB, cB);
        aB[1] = tile_addr(ba + 16384, rB, cB + 2);
#pragma unroll
        for (int ks = 0; ks < 2; ks++) {
            uint32_t ah[4][4], am[4][4], bh[4][2], bm[4][2];
#pragma unroll
            for (int mt = 0; mt < 4; mt++) {
                LDSM4(ah[mt][0], ah[mt][1], ah[mt][2], ah[mt][3], aA[ks] + mt * 1024);
                LDSM4(am[mt][0], am[mt][1], am[mt][2], am[mt][3], aA[ks] + 8192 + mt * 1024);
            }
#pragma unroll
            for (int p = 0; p < 2; p++) {
                LDSM4(bh[2*p][0], bh[2*p][1], bh[2*p+1][0], bh[2*p+1][1], aB[ks] + p * 1024);
                LDSM4(bm[2*p][0], bm[2*p][1], bm[2*p+1][0], bm[2*p+1][1],
                      aB[ks] + 8192 + p * 1024);
            }
#pragma unroll
            for (int mt = 0; mt < 4; mt++)
#pragma unroll
                for (int nt = 0; nt < 4; nt++) {
                    mma16816(acc[mt][nt], ah[mt], bh[nt]);
                    mma16816(acc[mt][nt], ah[mt], bm[nt]);
                    mma16816(acc[mt][nt], am[mt], bh[nt]);
                }
        }
    };

    // ---- prologue + pipelined mainloop (3 buffers, 2 in flight) ----
    load_stage(0, 0);
    CP_COMMIT();
    if (nch > 1) load_stage(1, 1);
    CP_COMMIT();

    int buf = 0, nbuf = 2;
    for (int c = 0; c < nch; c++) {
        CP_WAIT1();
        __syncthreads();
        const int nxt = c + 2;
        if (nxt < nch) load_stage(nbuf, nxt);
        CP_COMMIT();
        compute(buf);
        buf = (buf == 2) ? 0 : buf + 1;
        nbuf = (nbuf == 2) ? 0 : nbuf + 1;
    }

    // ======================= epilogues (runtime dispatch) ===================
    if (ga.epi == 2) {
        __syncthreads();
        float* sval = reinterpret_cast<float*>(smem);
        int*   sidx = reinterpret_cast<int*>(smem + 2048);
#pragma unroll
        for (int mt = 0; mt < 4; mt++)
#pragma unroll
            for (int hh = 0; hh < 2; hh++) {
                float bv = 3.4e38f; int bi = 0x7FFFFFFF;
#pragma unroll
                for (int nt = 0; nt < 4; nt++)
#pragma unroll
                    for (int j = 0; j < 2; j++) {
                        const int gn = n0 + wn + nt * 8 + tg * 2 + j;
                        float s = -2.f * acc[mt][nt][hh * 2 + j] + ga.bias[gn];
                        if (s < bv || (s == bv && gn < bi)) { bv = s; bi = gn; }
                    }
#pragma unroll
                for (int o = 1; o < 4; o <<= 1) {
                    float ov = __shfl_xor_sync(0xFFFFFFFF, bv, o);
                    int   oi = __shfl_xor_sync(0xFFFFFFFF, bi, o);
                    if (ov < bv || (ov == bv && oi < bi)) { bv = ov; bi = oi; }
                }
                const int lr = wm + mt * 16 + hh * 8 + gq;
                if (tg == 0) { sval[lr * 4 + (wid & 3)] = bv; sidx[lr * 4 + (wid & 3)] = bi; }
            }
        __syncthreads();
        if (tid < 128) {
            float bv = sval[tid * 4]; int bi = sidx[tid * 4];
#pragma unroll
            for (int w = 1; w < 4; w++) {
                float ov = sval[tid * 4 + w]; int oi = sidx[tid * 4 + w];
                if (ov < bv || (ov == bv && oi < bi)) { bv = ov; bi = oi; }
            }
            g_cval[(size_t)(m0 + tid) * 8 + blockIdx.x] = bv;
            g_cidx[(size_t)(m0 + tid) * 8 + blockIdx.x] = bi;
        }
        return;
    }

#pragma unroll
    for (int mt = 0; mt < 4; mt++)
#pragma unroll
        for (int nt = 0; nt < 4; nt++) {
            const int gn = n0 + wn + nt * 8 + tg * 2;
#pragma unroll
            for (int hh = 0; hh < 2; hh++) {
                const int gm = m0 + wm + mt * 16 + gq + hh * 8;
                float v0 = acc[mt][nt][hh * 2 + 0];
                float v1 = acc[mt][nt][hh * 2 + 1];
                if (ga.epi == 4) {
                    if (gn < ga.N)
                        *reinterpret_cast<float2*>(ga.Cf + (size_t)gm * ga.N + gn) =
                            make_float2(v0, v1);
                } else {
                    v0 += ga.bias[gn]; v1 += ga.bias[gn + 1];
                    if (ga.epi == 0) {
                        v0 = (v0 >= 0.f) ? v0 : ALPHA * v0;
                        v1 = (v1 >= 0.f) ? v1 : ALPHA * v1;
                    }
                    __half h0, m0h, h1, m1h;
                    splitf(v0, h0, m0h);
                    splitf(v1, h1, m1h);
                    __half2 hp; hp.x = h0; hp.y = h1;
                    __half2 mp; mp.x = m0h; mp.y = m1h;
                    *reinterpret_cast<__half2*>(ga.Ch + (size_t)gm * ga.N + gn) = hp;
                    *reinterpret_cast<__half2*>(ga.Cm + (size_t)gm * ga.N + gn) = mp;
                }
            }
        }
}

// ------------- x -> fp16 hi/mid with K padding ------------------------------
__global__ __launch_bounds__(256) void conv_x(const float* __restrict__ x)
{
    int i = blockIdx.x * 256 + threadIdx.x;
    if (i >= BATCH * KP1) return;
    int row = i / KP1, col = i - row * KP1;
    float v = (col < IN_DIM) ? x[(size_t)row * IN_DIM + col] : 0.f;
    __half h, m;
    splitf(v, h, m);
    g_xh[i] = h; g_xm[i] = m;
}

// ------------- weight transpose + split + pad: in[K][N] -> out[Nr][Kp] ------
__global__ __launch_bounds__(256) void conv_wt(
    const float* __restrict__ in, __half* __restrict__ oh,
    __half* __restrict__ om, int K, int N, int Kp, int Nr)
{
    __shared__ float t[32][33];
    const int kb = blockIdx.y * 32, nb = blockIdx.x * 32;
    const int x = threadIdx.x & 31, y4 = (threadIdx.x >> 5) * 4;
#pragma unroll
    for (int i = 0; i < 4; i++) {
        int k = kb + y4 + i, n = nb + x;
        t[y4 + i][x] = (k < K && n < N) ? in[(size_t)k * N + n] : 0.f;
    }
    __syncthreads();
#pragma unroll
    for (int i = 0; i < 4; i++) {
        int n = nb + y4 + i, k = kb + x;
        if (n < Nr && k < Kp) {
            __half h, m;
            splitf(t[x][y4 + i], h, m);
            oh[(size_t)n * Kp + k] = h;
            om[(size_t)n * Kp + k] = m;
        }
    }
}

// ------------- codebook prep: transpose + split + norms + zero loss ---------
__global__ __launch_bounds__(256) void vq_pre_kernel(const float* __restrict__ emb)
{
    const int j = blockIdx.x;
    const int tid = threadIdx.x;
    __shared__ float red[256];
    float s = 0.f;
    for (int d = tid; d < LATENT; d += 256) {
        float v = emb[(size_t)d * NUM_EMB + j];
        g_embT[(size_t)j * LATENT + d] = v;
        __half h, m;
        splitf(v, h, m);
        g_ebh[(size_t)j * LATENT + d] = h;
        g_ebm[(size_t)j * LATENT + d] = m;
        s += v * v;
    }
    red[tid] = s;
    __syncthreads();
    for (int o = 128; o > 0; o >>= 1) {
        if (tid < o) red[tid] += red[tid + o];
        __syncthreads();
    }
    if (tid == 0) g_embsq[j] = red[0];
    if (blockIdx.x == 0 && tid == 0) g_loss = 0.f;
}

// ------------- split-K reduce: rt = b4 + sum of 4 partials ------------------
__global__ __launch_bounds__(256) void reduce_rt(const float* __restrict__ b4)
{
    int i = blockIdx.x * 256 + threadIdx.x;
    if (i >= RT_STRIDE) return;
    int d = i % OUT_DIM;
    g_rt[i] = b4[d] + g_rtp[i] + g_rtp[i + RT_STRIDE]
            + g_rtp[i + 2 * RT_STRIDE] + g_rtp[i + 3 * RT_STRIDE];
}

// ------- final argmin over 8 candidates + loss + recon-table gather ---------
__global__ __launch_bounds__(256) void vq_select2(float* __restrict__ out)
{
    const int row = blockIdx.x * 8 + (threadIdx.x >> 5);
    const int lane = threadIdx.x & 31;
    float bv = 3.4e38f; int bi = 0x7FFFFFFF;
    if (lane < 8) { bv = g_cval[(size_t)row * 8 + lane]; bi = g_cidx[(size_t)row * 8 + lane]; }
#pragma unroll
    for (int o = 1; o < 8; o <<= 1) {
        float ov = __shfl_xor_sync(0xFFFFFFFF, bv, o);
        int   oi = __shfl_xor_sync(0xFFFFFFFF, bi, o);
        if (ov < bv || (ov == bv && oi < bi)) { bv = ov; bi = oi; }
    }
    const int j = __shfl_sync(0xFFFFFFFF, bi, 0);

    // loss partial: sum (emb_j - z)^2, z reconstructed from fp16 pair
    const float* e = g_embT + (size_t)j * LATENT;
    const __half* zhp = g_zh + (size_t)row * LATENT;
    const __half* zmp = g_zm + (size_t)row * LATENT;
    float ls = 0.f;
#pragma unroll 4
    for (int d = lane; d < LATENT; d += 32) {
        float zv = __half2float(zhp[d]) + __half2float(zmp[d]);
        float df = e[d] - zv;
        ls += df * df;
    }
#pragma unroll
    for (int o = 16; o > 0; o >>= 1)
        ls += __shfl_xor_sync(0xFFFFFFFF, ls, o);
    if (lane == 0) atomicAdd(&g_loss, ls);

    // recon = decoder table row
    const float2* rrow = reinterpret_cast<const float2*>(g_rt + (size_t)j * OUT_DIM);
    float2* orow = reinterpret_cast<float2*>(out + (size_t)row * OUT_DIM);
#pragma unroll 4
    for (int d = lane; d < OUT_DIM / 2; d += 32)
        orow[d] = rrow[d];
}

__global__ void finalize_kernel(float* __restrict__ out, long long pos)
{
    out[pos] = 1.25f * g_loss / (float)((long long)BATCH * LATENT);
}

// ---------------------------------------------------------------------------
extern "C" void kernel_launch(void* const* d_in, const int* in_sizes, int n_in,
                              void* d_out, int out_size)
{
    const float* x   = (const float*)d_in[0];
    const float* W1  = (const float*)d_in[1];
    const float* b1  = (const float*)d_in[2];
    const float* W2  = (const float*)d_in[3];
    const float* b2  = (const float*)d_in[4];
    const float* emb = (const float*)d_in[5];
    const float* W3  = (const float*)d_in[6];
    const float* b3  = (const float*)d_in[7];
    const float* W4  = (const float*)d_in[8];
    const float* b4  = (const float*)d_in[9];
    float* out = (float*)d_out;

    __half *xh, *xm, *hh, *hm, *zh, *zm, *ebh, *ebm, *hdh, *hdm;
    __half *w1h, *w1m, *w2h, *w2m, *w3h, *w3m, *w4h, *w4m;
    float *embsq, *rtp;
    cudaGetSymbolAddress((void**)&xh,  g_xh);  cudaGetSymbolAddress((void**)&xm,  g_xm);
    cudaGetSymbolAddress((void**)&hh,  g_hh);  cudaGetSymbolAddress((void**)&hm,  g_hm);
    cudaGetSymbolAddress((void**)&zh,  g_zh);  cudaGetSymbolAddress((void**)&zm,  g_zm);
    cudaGetSymbolAddress((void**)&ebh, g_ebh); cudaGetSymbolAddress((void**)&ebm, g_ebm);
    cudaGetSymbolAddress((void**)&hdh, g_hdh); cudaGetSymbolAddress((void**)&hdm, g_hdm);
    cudaGetSymbolAddress((void**)&w1h, g_w1h); cudaGetSymbolAddress((void**)&w1m, g_w1m);
    cudaGetSymbolAddress((void**)&w2h, g_w2h); cudaGetSymbolAddress((void**)&w2m, g_w2m);
    cudaGetSymbolAddress((void**)&w3h, g_w3h); cudaGetSymbolAddress((void**)&w3m, g_w3m);
    cudaGetSymbolAddress((void**)&w4h, g_w4h); cudaGetSymbolAddress((void**)&w4m, g_w4m);
    cudaGetSymbolAddress((void**)&embsq, g_embsq);
    cudaGetSymbolAddress((void**)&rtp, g_rtp);

    cudaFuncSetAttribute(tc_dual, cudaFuncAttributeMaxDynamicSharedMemorySize, SMEM_DYN);

    const dim3 blk(256);

    // 0. conversions / prep
    conv_x<<<(BATCH * KP1 + 255) / 256, blk>>>(x);
    conv_wt<<<dim3(H_ENC / 32,  KP1 / 32),    blk>>>(W1, w1h, w1m, IN_DIM, H_ENC,  KP1,    H_ENC);
    conv_wt<<<dim3(LATENT / 32, H_ENC / 32),  blk>>>(W2, w2h, w2m, H_ENC,  LATENT, H_ENC,  LATENT);
    conv_wt<<<dim3(H_DEC / 32,  LATENT / 32), blk>>>(W3, w3h, w3m, LATENT, H_DEC,  LATENT, H_DEC);
    conv_wt<<<dim3(NB4 / 32,    H_DEC / 32),  blk>>>(W4, w4h, w4m, H_DEC,  OUT_DIM, H_DEC, NB4);
    vq_pre_kernel<<<NUM_EMB, blk>>>(emb);

    // 1. GEMM1 (h = leaky(x@W1+b1)) + table1 (hd = leaky(emb@W3+b3)) merged
    {
        GArgs A1 = {xh, xm, w1h, w1m, b1, nullptr, hh, hm,
                    H_ENC, KP1, KP1, KP1, H_ENC / 128, 0};
        GArgs T1 = {ebh, ebm, w3h, w3m, b3, nullptr, hdh, hdm,
                    H_DEC, LATENT, LATENT, LATENT, H_DEC / 128, 0};
        tc_dual<<<dim3(16, 128 + 8), blk, SMEM_DYN>>>(A1, T1, 128);
    }
    // 2. GEMM2 (z = h@W2+b2 -> pairs) + table2 split-K partials merged
    {
        GArgs A2 = {hh, hm, w2h, w2m, b2, nullptr, zh, zm,
                    LATENT, H_ENC, H_ENC, H_ENC, LATENT / 128, 1};
        GArgs T2 = {hdh, hdm, w4h, w4m, nullptr, rtp, nullptr, nullptr,
                    OUT_DIM, 512, H_DEC, H_DEC, NB4 / 128, 4};
        tc_dual<<<dim3(6, 128 + 32), blk, SMEM_DYN>>>(A2, T2, 128);
    }
    // 3. VQ scores + fused per-block argmin
    {
        GArgs A3 = {zh, zm, ebh, ebm, embsq, nullptr, nullptr, nullptr,
                    NUM_EMB, LATENT, LATENT, LATENT, NUM_EMB / 128, 2};
        tc_dual<<<dim3(8, 128), blk, SMEM_DYN>>>(A3, A3, 128);
    }
    // 4. reduce split-K partials into recon table
    reduce_rt<<<(RT_STRIDE + 255) / 256, blk>>>(b4);
    // 5. final argmin + loss + recon gather
    vq_select2<<<BATCH / 8, blk>>>(out);
    // 6. scalar loss
    finalize_kernel<<<1, 1>>>(out, (long long)out_size - 1);
}